// round 15
// baseline (speedup 1.0000x reference)
#include <cuda_runtime.h>
#include <cuda_bf16.h>
#include <mma.h>
#include <math.h>

using namespace nvcuda;

// ---------------------------------------------------------------------------
// Problem constants
// ---------------------------------------------------------------------------
#define T_TOK  1024
#define HID    1024
#define NH     16
#define NKV    4
#define HD     64
#define QKV_N  1536
#define NE     64
#define NG     8
#define INTER  512
#define NA     (T_TOK*NG)
#define NA_PAD 16384

// GEMM tiling
#define BM 128
#define BN 128
#define BK 32
#define LDA_S 40
#define LDB_S 136
#define NST 3

// attention smem leading dim
#define LDH 72

// conversion split points (uint4 units of 8 floats)
#define WGU8   8388608LL          // NE*HID*1024/8
#define TOT8   12582912LL         // + NE*INTER*HID/8
#define QKV_HI 5242880LL
#define ATT_HI 9437184LL

// ---------------------------------------------------------------------------
// Scratch (static device globals)
// ---------------------------------------------------------------------------
__device__ __nv_bfloat16 g_hb   [T_TOK*HID];
__device__ float         g_qkv  [T_TOK*QKV_N];
__device__ __nv_bfloat16 g_qb   [T_TOK*NH*HD];
__device__ __nv_bfloat16 g_kb   [T_TOK*NKV*HD];
__device__ __nv_bfloat16 g_vb   [T_TOK*NKV*HD];
__device__ __nv_bfloat16 g_attnb[T_TOK*NH*HD];
__device__ float         g_h2   [T_TOK*HID];
__device__ __nv_bfloat16 g_h2b  [T_TOK*HID];
__device__ __nv_bfloat16 g_actb [NA_PAD*INTER];
__device__ int   g_cnt [NE];
__device__ int   g_off [NE];
__device__ int   g_fill[NE];
__device__ int   g_total;
__device__ int   g_selid[NA];
__device__ float g_selw [NA];
__device__ int   g_tok  [NA_PAD];
__device__ float g_w    [NA_PAD];
// bf16 weight mirrors
__device__ __nv_bfloat16 g_wqkvb[HID*QKV_N];
__device__ __nv_bfloat16 g_wob  [NH*HD*HID];
__device__ __nv_bfloat16 g_wgub [NE*HID*1024];
__device__ __nv_bfloat16 g_wdb  [NE*INTER*HID];

// ---------------------------------------------------------------------------
// WMMA types + async copy helpers
// ---------------------------------------------------------------------------
using FragA  = wmma::fragment<wmma::matrix_a, 16, 16, 16, __nv_bfloat16, wmma::row_major>;
using FragB  = wmma::fragment<wmma::matrix_b, 16, 16, 16, __nv_bfloat16, wmma::row_major>;
using FragC  = wmma::fragment<wmma::accumulator, 16, 16, 16, float>;

__device__ __forceinline__ void cp16(unsigned dst, const void* src) {
    asm volatile("cp.async.cg.shared.global [%0], [%1], 16;\n" :: "r"(dst), "l"(src));
}
__device__ __forceinline__ void cp16z(unsigned dst, const void* src, int valid) {
    asm volatile("cp.async.cg.shared.global [%0], [%1], 16, %2;\n"
                 :: "r"(dst), "l"(src), "r"(valid ? 16 : 0));
}
#define CP_COMMIT() asm volatile("cp.async.commit_group;\n")
template<int N> __device__ __forceinline__ void cp_wait() {
    asm volatile("cp.async.wait_group %0;\n" :: "n"(N));
}

__device__ __forceinline__ uint4 f8_to_bf8(float4 a, float4 b) {
    __nv_bfloat162 p0 = __floats2bfloat162_rn(a.x, a.y);
    __nv_bfloat162 p1 = __floats2bfloat162_rn(a.z, a.w);
    __nv_bfloat162 p2 = __floats2bfloat162_rn(b.x, b.y);
    __nv_bfloat162 p3 = __floats2bfloat162_rn(b.z, b.w);
    uint4 r;
    r.x = *reinterpret_cast<unsigned*>(&p0);
    r.y = *reinterpret_cast<unsigned*>(&p1);
    r.z = *reinterpret_cast<unsigned*>(&p2);
    r.w = *reinterpret_cast<unsigned*>(&p3);
    return r;
}

// piggyback conversion worker: convert uint4 units [lo, hi) of Wgu||Wd
__device__ __forceinline__ void conv_range(const float* __restrict__ Wgu,
                                           const float* __restrict__ Wd,
                                           long long lo, long long hi,
                                           long long start, long long stride) {
    __nv_bfloat16* wgub = g_wgub;
    __nv_bfloat16* wdb  = g_wdb;
    for (long long i = start; i < hi; i += stride) {
        const float* s; __nv_bfloat16* d; long long k;
        if (i < WGU8) { s = Wgu; d = wgub; k = i; }
        else          { s = Wd;  d = wdb;  k = i - WGU8; }
        const float4* p = (const float4*)s + k * 2;
        float4 a = p[0], b = p[1];
        *((uint4*)d + k) = f8_to_bf8(a, b);
    }
}

__device__ __forceinline__ void mma_tile(const __nv_bfloat16* As, const __nv_bfloat16* Bs,
                                         FragC (&acc)[2][4], int wm, int wn) {
#pragma unroll
    for (int kk = 0; kk < BK; kk += 16) {
        FragA a[2];
        FragB b[4];
#pragma unroll
        for (int i = 0; i < 2; i++)
            wmma::load_matrix_sync(a[i], As + (wm * 32 + i * 16) * LDA_S + kk, LDA_S);
#pragma unroll
        for (int j = 0; j < 4; j++)
            wmma::load_matrix_sync(b[j], Bs + kk * LDB_S + wn * 64 + j * 16, LDB_S);
#pragma unroll
        for (int i = 0; i < 2; i++)
#pragma unroll
            for (int j = 0; j < 4; j++)
                wmma::mma_sync(acc[i][j], a[i], b[j], acc[i][j]);
    }
}

// raw PTX mma/ldmatrix for attention
__device__ __forceinline__ void mma16816(float c[4], const unsigned a[4],
                                         unsigned b0, unsigned b1) {
    asm volatile(
        "mma.sync.aligned.m16n8k16.row.col.f32.bf16.bf16.f32 "
        "{%0,%1,%2,%3}, {%4,%5,%6,%7}, {%8,%9}, {%0,%1,%2,%3};\n"
        : "+f"(c[0]), "+f"(c[1]), "+f"(c[2]), "+f"(c[3])
        : "r"(a[0]), "r"(a[1]), "r"(a[2]), "r"(a[3]), "r"(b0), "r"(b1));
}
__device__ __forceinline__ void ldsm4(unsigned d[4], unsigned addr) {
    asm volatile("ldmatrix.sync.aligned.m8n8.x4.shared.b16 {%0,%1,%2,%3}, [%4];\n"
        : "=r"(d[0]), "=r"(d[1]), "=r"(d[2]), "=r"(d[3]) : "r"(addr));
}
__device__ __forceinline__ void ldsm4t(unsigned d[4], unsigned addr) {
    asm volatile("ldmatrix.sync.aligned.m8n8.x4.trans.shared.b16 {%0,%1,%2,%3}, [%4];\n"
        : "=r"(d[0]), "=r"(d[1]), "=r"(d[2]), "=r"(d[3]) : "r"(addr));
}

// ---------------------------------------------------------------------------
// fp32 -> bf16 streaming conversion (serial, small weights)
// ---------------------------------------------------------------------------
__global__ void k_f2b(const float* __restrict__ s, __nv_bfloat16* __restrict__ d, int n8) {
    int i = blockIdx.x * 256 + threadIdx.x;
    if (i >= n8) return;
    const float4* p = (const float4*)s + (size_t)i * 2;
    float4 a = p[0], b = p[1];
    *((uint4*)d + i) = f8_to_bf8(a, b);
}

// ---------------------------------------------------------------------------
// RMSNorm
// ---------------------------------------------------------------------------
__global__ void k_rmsnorm(const float* __restrict__ in,
                          const float* __restrict__ w,
                          float* __restrict__ outf,
                          __nv_bfloat16* __restrict__ outb) {
    int t = blockIdx.x;
    const float* x = in + (size_t)t * HID;
    float ss = 0.f;
    for (int i = threadIdx.x; i < HID; i += 256) { float v = x[i]; ss += v * v; }
#pragma unroll
    for (int o = 16; o; o >>= 1) ss += __shfl_xor_sync(0xffffffffu, ss, o);
    __shared__ float red[8];
    __shared__ float stot;
    if ((threadIdx.x & 31) == 0) red[threadIdx.x >> 5] = ss;
    __syncthreads();
    if (threadIdx.x == 0) {
        float s = 0.f;
#pragma unroll
        for (int i = 0; i < 8; i++) s += red[i];
        stot = rsqrtf(s * (1.f / HID) + 1e-6f);
    }
    __syncthreads();
    float sc = stot;
    for (int i = threadIdx.x; i < HID; i += 256) {
        float v = x[i] * sc * w[i];
        if (outf) outf[(size_t)t * HID + i] = v;
        if (outb) outb[(size_t)t * HID + i] = __float2bfloat16(v);
    }
}

// ---------------------------------------------------------------------------
// Dense bf16 GEMM, 3-stage cp.async (A bf16, B bf16) + conversion piggyback
// (blockIdx.z == 1 blocks are conversion workers).
// ---------------------------------------------------------------------------
__global__ void __launch_bounds__(256) k_gemm_bb(
        const __nv_bfloat16* __restrict__ A, const __nv_bfloat16* __restrict__ B,
        float* __restrict__ C, const float* __restrict__ R,
        int M, int N, int K,
        const float* __restrict__ cWgu, const float* __restrict__ cWd,
        long long clo, long long chi) {
    if (blockIdx.z == 1) {
        long long wid = blockIdx.y * gridDim.x + blockIdx.x;
        long long nw  = (long long)gridDim.x * gridDim.y;
        conv_range(cWgu, cWd, clo, chi,
                   clo + wid * 256 + threadIdx.x, nw * 256);
        return;
    }
    __shared__ __nv_bfloat16 As[NST][BM * LDA_S];
    __shared__ __nv_bfloat16 Bs[NST][BK * LDB_S];
    int tid = threadIdx.x;
    int warp = tid >> 5;
    int wm = warp & 3, wn = warp >> 2;
    int m0 = blockIdx.y * BM, n0 = blockIdx.x * BN;

    int ar = tid >> 2, ac = (tid & 3) * 8;
    int br = tid >> 4, bc = (tid & 15) * 8;
    const __nv_bfloat16* a0 = A + (size_t)(m0 + ar) * K + ac;
    const __nv_bfloat16* a1 = A + (size_t)(m0 + ar + 64) * K + ac;
    const __nv_bfloat16* b0 = B + (size_t)br * N + n0 + bc;
    const __nv_bfloat16* b1 = B + (size_t)(br + 16) * N + n0 + bc;
    unsigned dA0 = (unsigned)__cvta_generic_to_shared(&As[0][ar * LDA_S + ac]);
    unsigned dA1 = (unsigned)__cvta_generic_to_shared(&As[0][(ar + 64) * LDA_S + ac]);
    unsigned dB0 = (unsigned)__cvta_generic_to_shared(&Bs[0][br * LDB_S + bc]);
    unsigned dB1 = (unsigned)__cvta_generic_to_shared(&Bs[0][(br + 16) * LDB_S + bc]);
    const unsigned szA = BM * LDA_S * 2, szB = BK * LDB_S * 2;

    FragC acc[2][4];
    if (R) {
#pragma unroll
        for (int i = 0; i < 2; i++)
#pragma unroll
            for (int j = 0; j < 4; j++)
                wmma::load_matrix_sync(acc[i][j],
                    R + (size_t)(m0 + wm * 32 + i * 16) * N + n0 + wn * 64 + j * 16,
                    N, wmma::mem_row_major);
    } else {
#pragma unroll
        for (int i = 0; i < 2; i++)
#pragma unroll
            for (int j = 0; j < 4; j++) wmma::fill_fragment(acc[i][j], 0.f);
    }

    auto cpS = [&](int st, int k0) {
        cp16(dA0 + st * szA, a0 + k0);
        cp16(dA1 + st * szA, a1 + k0);
        cp16(dB0 + st * szB, b0 + (size_t)k0 * N);
        cp16(dB1 + st * szB, b1 + (size_t)k0 * N);
    };

    const int niter = K / BK;
    cpS(0, 0); CP_COMMIT();
    cpS(1, BK); CP_COMMIT();
    cp_wait<1>(); __syncthreads();
    int sc = 0;
    for (int it = 0; it < niter; it++) {
        mma_tile(As[sc], Bs[sc], acc, wm, wn);
        if (it + 2 < niter) {
            int sp = sc + 2 >= NST ? sc + 2 - NST : sc + 2;
            cpS(sp, (it + 2) * BK); CP_COMMIT();
            cp_wait<1>();
        } else cp_wait<0>();
        __syncthreads();
        sc = (sc + 1 == NST) ? 0 : sc + 1;
    }
#pragma unroll
    for (int i = 0; i < 2; i++)
#pragma unroll
        for (int j = 0; j < 4; j++)
            wmma::store_matrix_sync(
                C + (size_t)(m0 + wm * 32 + i * 16) * N + n0 + wn * 64 + j * 16,
                acc[i][j], N, wmma::mem_row_major);
}

// ---------------------------------------------------------------------------
// Per-head RMSNorm + RoPE (q,k) and copy (v) -> bf16
// ---------------------------------------------------------------------------
__global__ void k_qk_prep(const int* __restrict__ pos,
                          const float* __restrict__ qnw,
                          const float* __restrict__ knw) {
    int hh = blockIdx.x;
    int t  = blockIdx.y;
    int i  = threadIdx.x;
    if (hh >= NH + NKV) {
        int vh = hh - NH - NKV;
        const float* src = g_qkv + (size_t)t * QKV_N + (NH + NKV) * HD + vh * HD;
        __nv_bfloat16* dst = g_vb + (size_t)t * (NKV * HD) + vh * HD;
        dst[i]      = __float2bfloat16(src[i]);
        dst[i + 32] = __float2bfloat16(src[i + 32]);
        return;
    }
    const float* src; __nv_bfloat16* dst; const float* w;
    if (hh < NH) {
        src = g_qkv + (size_t)t * QKV_N + hh * HD;
        dst = g_qb  + (size_t)t * (NH * HD) + hh * HD;
        w = qnw;
    } else {
        int kh = hh - NH;
        src = g_qkv + (size_t)t * QKV_N + NH * HD + kh * HD;
        dst = g_kb  + (size_t)t * (NKV * HD) + kh * HD;
        w = knw;
    }
    float x1 = src[i], x2 = src[i + 32];
    float ss = x1 * x1 + x2 * x2;
#pragma unroll
    for (int o = 16; o; o >>= 1) ss += __shfl_xor_sync(0xffffffffu, ss, o);
    float sc = rsqrtf(ss * (1.f / 64.f) + 1e-6f);
    x1 *= sc * w[i];
    x2 *= sc * w[i + 32];
    float p = (float)pos[t];
    float inv = powf(10000.f, -(float)i * (1.f / 32.f));
    float f = p * inv;
    float c = cosf(f), s = sinf(f);
    dst[i]      = __float2bfloat16(x1 * c - x2 * s);
    dst[i + 32] = __float2bfloat16(x2 * c + x1 * s);
}

// ---------------------------------------------------------------------------
// Flash attention (register FA2) + conversion piggyback rows (blockIdx.y >= NH)
// ---------------------------------------------------------------------------
__global__ void __launch_bounds__(128) k_attn_mma(const float* __restrict__ cWgu,
                                                  const float* __restrict__ cWd) {
    if (blockIdx.y >= NH) {
        long long wid = (long long)(blockIdx.y - NH) * gridDim.x + blockIdx.x;  // 0..127
        conv_range(cWgu, cWd, QKV_HI, ATT_HI,
                   QKV_HI + wid * 128 + threadIdx.x, 128LL * 128LL);
        return;
    }
    __shared__ __nv_bfloat16 Qs[64 * LDH];
    __shared__ __nv_bfloat16 Ks[64 * LDH];
    __shared__ __nv_bfloat16 Vs[64 * LDH];
    int h = blockIdx.y, qt = blockIdx.x;
    int m0 = qt * 64, kvh = h >> 2;
    int tid = threadIdx.x, warp = tid >> 5, lane = tid & 31;
    int g = lane >> 3, li = lane & 7;

#pragma unroll
    for (int j = 0; j < 4; j++) {
        int idx = tid + j * 128;
        int r = idx >> 3, c = (idx & 7) * 8;
        *(uint4*)&Qs[r * LDH + c] =
            *(const uint4*)&g_qb[(size_t)(m0 + r) * (NH * HD) + h * HD + c];
    }
    __syncthreads();

    unsigned qa[4][4];
    {
        int row = warp * 16 + (g & 1) * 8 + li;
        int colg = (g >> 1) * 8;
#pragma unroll
        for (int hc = 0; hc < 4; hc++)
            ldsm4(qa[hc], (unsigned)__cvta_generic_to_shared(&Qs[row * LDH + hc * 16 + colg]));
    }

    float o[8][4];
#pragma unroll
    for (int f = 0; f < 8; f++) { o[f][0] = o[f][1] = o[f][2] = o[f][3] = 0.f; }
    float mr0 = -INFINITY, mr1 = -INFINITY, l0 = 0.f, l1 = 0.f;
    int R0 = m0 + warp * 16 + (lane >> 2);
    int R1 = R0 + 8;

    for (int nt = 0; nt <= qt; nt++) {
        int n0 = nt * 64;
        __syncthreads();
#pragma unroll
        for (int j = 0; j < 4; j++) {
            int idx = tid + j * 128;
            int r = idx >> 3, c = (idx & 7) * 8;
            *(uint4*)&Ks[r * LDH + c] =
                *(const uint4*)&g_kb[(size_t)(n0 + r) * (NKV * HD) + kvh * HD + c];
            *(uint4*)&Vs[r * LDH + c] =
                *(const uint4*)&g_vb[(size_t)(n0 + r) * (NKV * HD) + kvh * HD + c];
        }
        __syncthreads();

        float s[8][4];
#pragma unroll
        for (int f = 0; f < 8; f++) { s[f][0] = s[f][1] = s[f][2] = s[f][3] = 0.f; }
#pragma unroll
        for (int hc = 0; hc < 4; hc++) {
#pragma unroll
            for (int ng = 0; ng < 4; ng++) {
                unsigned d[4];
                int row = ng * 16 + (g >> 1) * 8 + li;
                int col = hc * 16 + (g & 1) * 8;
                ldsm4(d, (unsigned)__cvta_generic_to_shared(&Ks[row * LDH + col]));
                mma16816(s[2 * ng],     qa[hc], d[0], d[1]);
                mma16816(s[2 * ng + 1], qa[hc], d[2], d[3]);
            }
        }

        bool diag = (nt == qt);
        float mx0 = -INFINITY, mx1 = -INFINITY;
#pragma unroll
        for (int f = 0; f < 8; f++) {
            int cb = n0 + f * 8 + (lane & 3) * 2;
            s[f][0] *= 0.125f; s[f][1] *= 0.125f;
            s[f][2] *= 0.125f; s[f][3] *= 0.125f;
            if (diag) {
                if (cb     > R0) s[f][0] = -INFINITY;
                if (cb + 1 > R0) s[f][1] = -INFINITY;
                if (cb     > R1) s[f][2] = -INFINITY;
                if (cb + 1 > R1) s[f][3] = -INFINITY;
            }
            mx0 = fmaxf(mx0, fmaxf(s[f][0], s[f][1]));
            mx1 = fmaxf(mx1, fmaxf(s[f][2], s[f][3]));
        }
        mx0 = fmaxf(mx0, __shfl_xor_sync(0xffffffffu, mx0, 1));
        mx0 = fmaxf(mx0, __shfl_xor_sync(0xffffffffu, mx0, 2));
        mx1 = fmaxf(mx1, __shfl_xor_sync(0xffffffffu, mx1, 1));
        mx1 = fmaxf(mx1, __shfl_xor_sync(0xffffffffu, mx1, 2));
        float mn0 = fmaxf(mr0, mx0), mn1 = fmaxf(mr1, mx1);
        float al0 = __expf(mr0 - mn0), al1 = __expf(mr1 - mn1);
        mr0 = mn0; mr1 = mn1;

        unsigned P[4][4];
        float ps0 = 0.f, ps1 = 0.f;
#pragma unroll
        for (int f = 0; f < 8; f++) {
            float p0 = __expf(s[f][0] - mn0);
            float p1 = __expf(s[f][1] - mn0);
            float p2 = __expf(s[f][2] - mn1);
            float p3 = __expf(s[f][3] - mn1);
            ps0 += p0 + p1; ps1 += p2 + p3;
            __nv_bfloat162 b0 = __floats2bfloat162_rn(p0, p1);
            __nv_bfloat162 b1 = __floats2bfloat162_rn(p2, p3);
            P[f >> 1][(f & 1) * 2]     = *reinterpret_cast<unsigned*>(&b0);
            P[f >> 1][(f & 1) * 2 + 1] = *reinterpret_cast<unsigned*>(&b1);
        }
        ps0 += __shfl_xor_sync(0xffffffffu, ps0, 1);
        ps0 += __shfl_xor_sync(0xffffffffu, ps0, 2);
        ps1 += __shfl_xor_sync(0xffffffffu, ps1, 1);
        ps1 += __shfl_xor_sync(0xffffffffu, ps1, 2);
        l0 = l0 * al0 + ps0;
        l1 = l1 * al1 + ps1;
#pragma unroll
        for (int f = 0; f < 8; f++) {
            o[f][0] *= al0; o[f][1] *= al0;
            o[f][2] *= al1; o[f][3] *= al1;
        }

#pragma unroll
        for (int c = 0; c < 4; c++) {
#pragma unroll
            for (int j = 0; j < 4; j++) {
                unsigned d[4];
                int row = c * 16 + (g & 1) * 8 + li;
                int col = j * 16 + (g >> 1) * 8;
                ldsm4t(d, (unsigned)__cvta_generic_to_shared(&Vs[row * LDH + col]));
                mma16816(o[2 * j],     P[c], d[0], d[1]);
                mma16816(o[2 * j + 1], P[c], d[2], d[3]);
            }
        }
    }

    float i0 = 1.f / l0, i1 = 1.f / l1;
#pragma unroll
    for (int f = 0; f < 8; f++) {
        int col = h * HD + f * 8 + (lane & 3) * 2;
        __nv_bfloat162 v0 = __floats2bfloat162_rn(o[f][0] * i0, o[f][1] * i0);
        __nv_bfloat162 v1 = __floats2bfloat162_rn(o[f][2] * i1, o[f][3] * i1);
        *(unsigned*)&g_attnb[(size_t)R0 * (NH * HD) + col] = *reinterpret_cast<unsigned*>(&v0);
        *(unsigned*)&g_attnb[(size_t)R1 * (NH * HD) + col] = *reinterpret_cast<unsigned*>(&v1);
    }
}

// ---------------------------------------------------------------------------
// Routing
// ---------------------------------------------------------------------------
__global__ void k_zero() {
    int i = threadIdx.x;
    if (i < NE) { g_cnt[i] = 0; g_fill[i] = 0; }
}

__global__ void k_route(const float* __restrict__ H2, const float* __restrict__ Wg) {
    int t = blockIdx.x;
    int e = threadIdx.x;
    __shared__ float sh[HID];
    for (int i = e; i < HID; i += 64) sh[i] = H2[(size_t)t * HID + i];
    __syncthreads();
    float a0 = 0, a1 = 0, a2 = 0, a3 = 0;
    for (int k = 0; k < HID; k += 4) {
        a0 += sh[k]     * Wg[(size_t)k       * NE + e];
        a1 += sh[k + 1] * Wg[(size_t)(k + 1) * NE + e];
        a2 += sh[k + 2] * Wg[(size_t)(k + 2) * NE + e];
        a3 += sh[k + 3] * Wg[(size_t)(k + 3) * NE + e];
    }
    __shared__ float logits[NE];
    logits[e] = (a0 + a1) + (a2 + a3);
    __syncthreads();
    if (e == 0) {
        float sv[NG]; int si[NG];
#pragma unroll
        for (int gg = 0; gg < NG; gg++) {
            float best = logits[gg * 8]; int bi = gg * 8;
#pragma unroll
            for (int j = 1; j < 8; j++) {
                float v = logits[gg * 8 + j];
                if (v > best) { best = v; bi = gg * 8 + j; }
            }
            sv[gg] = best; si[gg] = bi;
        }
        float m = sv[0];
#pragma unroll
        for (int gg = 1; gg < NG; gg++) m = fmaxf(m, sv[gg]);
        float sum = 0.f, p[NG];
#pragma unroll
        for (int gg = 0; gg < NG; gg++) { p[gg] = expf(sv[gg] - m); sum += p[gg]; }
        float is = 1.f / sum;
#pragma unroll
        for (int gg = 0; gg < NG; gg++) {
            g_selid[t * NG + gg] = si[gg];
            g_selw [t * NG + gg] = p[gg] * is;
            atomicAdd(&g_cnt[si[gg]], 1);
        }
    }
}

__global__ void k_scan() {
    int s = 0;
    for (int e = 0; e < NE; e++) { g_off[e] = s; s += (g_cnt[e] + BM - 1) & ~(BM - 1); }
    g_total = s;
}

__global__ void k_scatter() {
    int t = blockIdx.x, gg = threadIdx.x;
    int e = g_selid[t * NG + gg];
    int slot = atomicAdd(&g_fill[e], 1);
    int row = g_off[e] + slot;
    g_tok[row] = t;
    g_w[row]   = g_selw[t * NG + gg];
}

// ---------------------------------------------------------------------------
// MoE GEMM 1 (bf16 weights, 3-stage cp.async) + fused silu epilogue.
// ---------------------------------------------------------------------------
#define MOE1_SMEM (128*132*4)   // 67584 >= pipeline (56832)
__global__ void __launch_bounds__(256) k_moe1(const __nv_bfloat16* __restrict__ Ab,
                                              const __nv_bfloat16* __restrict__ Bw) {
    extern __shared__ __align__(16) char sraw[];
    __shared__ int stok[BM];
    __nv_bfloat16* As = (__nv_bfloat16*)sraw;
    __nv_bfloat16* Bs = As + NST * BM * LDA_S;
    float* Ebuf = (float*)sraw;

    int e = blockIdx.z;
    int cnt = g_cnt[e];
    int m0 = blockIdx.y * BM;
    if (m0 >= cnt) return;
    int off = g_off[e];
    int n0 = blockIdx.x * 64;
    const __nv_bfloat16* B = Bw + (size_t)e * (HID * 1024);

    int tid = threadIdx.x;
    int warp = tid >> 5;
    int wm = warp & 3, wn = warp >> 2;
    if (tid < BM) stok[tid] = (m0 + tid < cnt) ? g_tok[off + m0 + tid] : -1;
    __syncthreads();

    int ar = tid >> 2, ac = (tid & 3) * 8;
    int br = tid >> 4, bc = (tid & 15) * 8;
    int tk0 = stok[ar], tk1 = stok[ar + 64];
    const __nv_bfloat16* a0 = Ab + (size_t)((tk0 >= 0) ? tk0 : 0) * HID + ac;
    const __nv_bfloat16* a1 = Ab + (size_t)((tk1 >= 0) ? tk1 : 0) * HID + ac;
    int colg = (bc < 64) ? (n0 + bc) : (512 + n0 + bc - 64);
    const __nv_bfloat16* b0 = B + (size_t)br * 1024 + colg;
    const __nv_bfloat16* b1 = B + (size_t)(br + 16) * 1024 + colg;
    unsigned dA0 = (unsigned)__cvta_generic_to_shared(&As[ar * LDA_S + ac]);
    unsigned dA1 = (unsigned)__cvta_generic_to_shared(&As[(ar + 64) * LDA_S + ac]);
    unsigned dB0 = (unsigned)__cvta_generic_to_shared(&Bs[br * LDB_S + bc]);
    unsigned dB1 = (unsigned)__cvta_generic_to_shared(&Bs[(br + 16) * LDB_S + bc]);
    const unsigned szA = BM * LDA_S * 2, szB = BK * LDB_S * 2;

    FragC acc[2][4];
#pragma unroll
    for (int i = 0; i < 2; i++)
#pragma unroll
        for (int j = 0; j < 4; j++) wmma::fill_fragment(acc[i][j], 0.f);

    auto cpS = [&](int st, int k0) {
        cp16z(dA0 + st * szA, a0 + k0, tk0 >= 0);
        cp16z(dA1 + st * szA, a1 + k0, tk1 >= 0);
        cp16(dB0 + st * szB, b0 + (size_t)k0 * 1024);
        cp16(dB1 + st * szB, b1 + (size_t)k0 * 1024);
    };

    const int niter = HID / BK;
    cpS(0, 0); CP_COMMIT();
    cpS(1, BK); CP_COMMIT();
    cp_wait<1>(); __syncthreads();
    int sc = 0;
    for (int it = 0; it < niter; it++) {
        mma_tile(As + sc * BM * LDA_S, Bs + sc * BK * LDB_S, acc, wm, wn);
        if (it + 2 < niter) {
            int sp = sc + 2 >= NST ? sc + 2 - NST : sc + 2;
            cpS(sp, (it + 2) * BK); CP_COMMIT();
            cp_wait<1>();
        } else cp_wait<0>();
        __syncthreads();
        sc = (sc + 1 == NST) ? 0 : sc + 1;
    }

    // fused activation epilogue (stage C in aliased smem)
    __syncthreads();
#pragma unroll
    for (int i = 0; i < 2; i++)
#pragma unroll
        for (int j = 0; j < 4; j++)
            wmma::store_matrix_sync(Ebuf + (wm * 32 + i * 16) * 132 + wn * 64 + j * 16,
                                    acc[i][j], 132, wmma::mem_row_major);
    __syncthreads();

    int r  = tid >> 1;
    int c0 = (tid & 1) * 32;
    float wt = (m0 + r < cnt) ? g_w[off + m0 + r] : 0.f;
    unsigned vals[16];
#pragma unroll
    for (int q = 0; q < 16; q++) {
        float g0 = Ebuf[r * 132 + c0 + q * 2];
        float g1 = Ebuf[r * 132 + c0 + q * 2 + 1];
        float u0 = Ebuf[r * 132 + 64 + c0 + q * 2];
        float u1 = Ebuf[r * 132 + 64 + c0 + q * 2 + 1];
        float x0 = g0 / (1.f + __expf(-g0)) * u0 * wt;
        float x1 = g1 / (1.f + __expf(-g1)) * u1 * wt;
        __nv_bfloat162 p = __floats2bfloat162_rn(x0, x1);
        vals[q] = *reinterpret_cast<unsigned*>(&p);
    }
    uint4* dst = (uint4*)&g_actb[(size_t)(off + m0 + r) * INTER + n0 + c0];
#pragma unroll
    for (int q = 0; q < 4; q++)
        dst[q] = make_uint4(vals[q * 4], vals[q * 4 + 1], vals[q * 4 + 2], vals[q * 4 + 3]);
}

// ---------------------------------------------------------------------------
// MoE GEMM 2 (bf16 weights, 3-stage cp.async), staged atomic scatter-add.
// ---------------------------------------------------------------------------
__global__ void __launch_bounds__(256) k_moe2(const __nv_bfloat16* __restrict__ Bw,
                                              float* __restrict__ out) {
    __shared__ __nv_bfloat16 As[NST][BM * LDA_S];
    __shared__ __nv_bfloat16 Bs[NST][BK * LDB_S];
    __shared__ float stage_s[8 * 272];
    __shared__ int stok[BM];

    int e = blockIdx.z;
    int cnt = g_cnt[e];
    int m0 = blockIdx.y * BM;
    if (m0 >= cnt) return;
    int off = g_off[e];
    int n0 = blockIdx.x * BN;
    const __nv_bfloat16* B = Bw + (size_t)e * (INTER * HID);

    int tid = threadIdx.x;
    int lane = tid & 31;
    int warp = tid >> 5;
    int wm = warp & 3, wn = warp >> 2;
    if (tid < BM) stok[tid] = (m0 + tid < cnt) ? g_tok[off + m0 + tid] : -1;
    __syncthreads();

    int ar = tid >> 2, ac = (tid & 3) * 8;
    int br = tid >> 4, bc = (tid & 15) * 8;
    const __nv_bfloat16* a0 = g_actb + (size_t)(off + m0 + ar) * INTER + ac;
    const __nv_bfloat16* a1 = g_actb + (size_t)(off + m0 + ar + 64) * INTER + ac;
    const __nv_bfloat16* b0 = B + (size_t)br * HID + n0 + bc;
    const __nv_bfloat16* b1 = B + (size_t)(br + 16) * HID + n0 + bc;
    unsigned dA0 = (unsigned)__cvta_generic_to_shared(&As[0][ar * LDA_S + ac]);
    unsigned dA1 = (unsigned)__cvta_generic_to_shared(&As[0][(ar + 64) * LDA_S + ac]);
    unsigned dB0 = (unsigned)__cvta_generic_to_shared(&Bs[0][br * LDB_S + bc]);
    unsigned dB1 = (unsigned)__cvta_generic_to_shared(&Bs[0][(br + 16) * LDB_S + bc]);
    const unsigned szA = BM * LDA_S * 2, szB = BK * LDB_S * 2;

    FragC acc[2][4];
#pragma unroll
    for (int i = 0; i < 2; i++)
#pragma unroll
        for (int j = 0; j < 4; j++) wmma::fill_fragment(acc[i][j], 0.f);

    auto cpS = [&](int st, int k0) {
        cp16(dA0 + st * szA, a0 + k0);
        cp16(dA1 + st * szA, a1 + k0);
        cp16(dB0 + st * szB, b0 + (size_t)k0 * HID);
        cp16(dB1 + st * szB, b1 + (size_t)k0 * HID);
    };

    const int niter = INTER / BK;
    cpS(0, 0); CP_COMMIT();
    cpS(1, BK); CP_COMMIT();
    cp_wait<1>(); __syncthreads();
    int sc = 0;
    for (int it = 0; it < niter; it++) {
        mma_tile(As[sc], Bs[sc], acc, wm, wn);
        if (it + 2 < niter) {
            int sp = sc + 2 >= NST ? sc + 2 - NST : sc + 2;
            cpS(sp, (it + 2) * BK); CP_COMMIT();
            cp_wait<1>();
        } else cp_wait<0>();
        __syncthreads();
        sc = (sc + 1 == NST) ? 0 : sc + 1;
    }

#pragma unroll
    for (int i = 0; i < 2; i++) {
#pragma unroll
        for (int j = 0; j < 4; j++) {
            wmma::store_matrix_sync(&stage_s[warp * 272], acc[i][j], 16, wmma::mem_row_major);
            __syncwarp();
#pragma unroll
            for (int q = 0; q < 8; q++) {
                int el = lane + q * 32;
                int r = el >> 4, c = el & 15;
                int lr = wm * 32 + i * 16 + r;
                if (m0 + lr < cnt) {
                    int tk = stok[lr];
                    atomicAdd(&out[(size_t)tk * HID + n0 + wn * 64 + j * 16 + c],
                              stage_s[warp * 272 + r * 16 + c]);
                }
            }
            __syncwarp();
        }
    }
}

// ---------------------------------------------------------------------------
// Launch
// ---------------------------------------------------------------------------
extern "C" void kernel_launch(void* const* d_in, const int* in_sizes, int n_in,
                              void* d_out, int out_size) {
    const int*   positions = (const int*)  d_in[0];
    const float* hidden    = (const float*)d_in[1];
    const float* Wqkv      = (const float*)d_in[2];
    const float* Wo        = (const float*)d_in[3];
    const float* qnw       = (const float*)d_in[4];
    const float* knw       = (const float*)d_in[5];
    const float* inln      = (const float*)d_in[6];
    const float* postln    = (const float*)d_in[7];
    const float* Wg        = (const float*)d_in[8];
    const float* Wgu       = (const float*)d_in[9];
    const float* Wd        = (const float*)d_in[10];
    float* out = (float*)d_out;

    __nv_bfloat16 *p_hb, *p_attnb, *p_h2b, *p_wqkvb, *p_wob, *p_wgub, *p_wdb;
    float *p_qkv, *p_h2;
    cudaGetSymbolAddress((void**)&p_hb,    g_hb);
    cudaGetSymbolAddress((void**)&p_qkv,   g_qkv);
    cudaGetSymbolAddress((void**)&p_h2,    g_h2);
    cudaGetSymbolAddress((void**)&p_h2b,   g_h2b);
    cudaGetSymbolAddress((void**)&p_attnb, g_attnb);
    cudaGetSymbolAddress((void**)&p_wqkvb, g_wqkvb);
    cudaGetSymbolAddress((void**)&p_wob,   g_wob);
    cudaGetSymbolAddress((void**)&p_wgub,  g_wgub);
    cudaGetSymbolAddress((void**)&p_wdb,   g_wdb);

    cudaFuncSetAttribute(k_moe1, cudaFuncAttributeMaxDynamicSharedMemorySize, MOE1_SMEM);

    // 0. small weight conversions (serial, ~3 us)
    k_f2b<<<(HID * QKV_N / 8 + 255) / 256, 256>>>(Wqkv, p_wqkvb, HID * QKV_N / 8);
    k_f2b<<<(NH * HD * HID / 8 + 255) / 256, 256>>>(Wo, p_wob, NH * HD * HID / 8);

    // 1. pre-attn rmsnorm (bf16)
    k_rmsnorm<<<T_TOK, 256>>>(hidden, inln, nullptr, p_hb);
    // 2. qkv projection (+ Wgu/Wd conversion workers, units [0, QKV_HI))
    k_gemm_bb<<<dim3(QKV_N / BN, T_TOK / BM, 2), 256>>>(
        p_hb, p_wqkvb, p_qkv, nullptr, T_TOK, QKV_N, HID, Wgu, Wd, 0LL, QKV_HI);
    // 3. per-head rmsnorm + rope + v convert
    k_qk_prep<<<dim3(NH + 2 * NKV, T_TOK), 32>>>(positions, qnw, knw);
    // 4. causal flash attention (+ conversion workers, units [QKV_HI, ATT_HI))
    k_attn_mma<<<dim3(T_TOK / 64, NH + 8), 128>>>(Wgu, Wd);
    // 5. x = resid + attn @ Wo (+ conversion workers, units [ATT_HI, TOT8))
    k_gemm_bb<<<dim3(HID / BN, T_TOK / BM, 2), 256>>>(
        p_attnb, p_wob, out, hidden, T_TOK, HID, NH * HD, Wgu, Wd, ATT_HI, TOT8);
    // 6. post-attn rmsnorm
    k_rmsnorm<<<T_TOK, 256>>>(out, postln, p_h2, p_h2b);
    // 7-10. routing
    k_zero<<<1, 64>>>();
    k_route<<<T_TOK, 64>>>(p_h2, Wg);
    k_scan<<<1, 1>>>();
    k_scatter<<<T_TOK, 8>>>();
    // 11. grouped gate_up GEMM (bf16 weights, 3-stage) + fused activation
    k_moe1<<<dim3(8, 8, NE), 256, MOE1_SMEM>>>(p_h2b, p_wgub);
    // 12. grouped down GEMM (bf16 weights, 3-stage), scatter-add into d_out
    k_moe2<<<dim3(HID / BN, 8, NE), 256>>>(p_wdb, out);
}

// round 16
// speedup vs baseline: 1.0954x; 1.0954x over previous
#include <cuda_runtime.h>
#include <cuda_bf16.h>
#include <mma.h>
#include <math.h>

using namespace nvcuda;

// ---------------------------------------------------------------------------
// Problem constants
// ---------------------------------------------------------------------------
#define T_TOK  1024
#define HID    1024
#define NH     16
#define NKV    4
#define HD     64
#define QKV_N  1536
#define NE     64
#define NG     8
#define INTER  512
#define NA     (T_TOK*NG)
#define NA_PAD 16384

// GEMM tiling
#define BM 128
#define BN 128
#define BK 32
#define LDA_S 40
#define LDB_S 136

// attention smem leading dim
#define LDH 72

// ---------------------------------------------------------------------------
// Scratch (static device globals)
// ---------------------------------------------------------------------------
__device__ __nv_bfloat16 g_hb   [T_TOK*HID];
__device__ float         g_qkv  [T_TOK*QKV_N];
__device__ __nv_bfloat16 g_qb   [T_TOK*NH*HD];
__device__ __nv_bfloat16 g_kb   [T_TOK*NKV*HD];
__device__ __nv_bfloat16 g_vb   [T_TOK*NKV*HD];
__device__ __nv_bfloat16 g_attnb[T_TOK*NH*HD];
__device__ float         g_h2   [T_TOK*HID];
__device__ __nv_bfloat16 g_h2b  [T_TOK*HID];
__device__ __nv_bfloat16 g_actb [NA_PAD*INTER];
__device__ int   g_cnt [NE];
__device__ int   g_off [NE];
__device__ int   g_fill[NE];
__device__ int   g_total;
__device__ int   g_selid[NA];
__device__ float g_selw [NA];
__device__ int   g_tok  [NA_PAD];
__device__ float g_w    [NA_PAD];

// ---------------------------------------------------------------------------
// WMMA types + helpers
// ---------------------------------------------------------------------------
using FragA  = wmma::fragment<wmma::matrix_a, 16, 16, 16, __nv_bfloat16, wmma::row_major>;
using FragB  = wmma::fragment<wmma::matrix_b, 16, 16, 16, __nv_bfloat16, wmma::row_major>;
using FragC  = wmma::fragment<wmma::accumulator, 16, 16, 16, float>;

__device__ __forceinline__ void cp16(unsigned dst, const void* src) {
    asm volatile("cp.async.cg.shared.global [%0], [%1], 16;\n" :: "r"(dst), "l"(src));
}
__device__ __forceinline__ void cp16z(unsigned dst, const void* src, int valid) {
    asm volatile("cp.async.cg.shared.global [%0], [%1], 16, %2;\n"
                 :: "r"(dst), "l"(src), "r"(valid ? 16 : 0));
}
#define CP_COMMIT() asm volatile("cp.async.commit_group;\n")
template<int N> __device__ __forceinline__ void cp_wait() {
    asm volatile("cp.async.wait_group %0;\n" :: "n"(N));
}

__device__ __forceinline__ uint4 f8_to_bf8(float4 a, float4 b) {
    __nv_bfloat162 p0 = __floats2bfloat162_rn(a.x, a.y);
    __nv_bfloat162 p1 = __floats2bfloat162_rn(a.z, a.w);
    __nv_bfloat162 p2 = __floats2bfloat162_rn(b.x, b.y);
    __nv_bfloat162 p3 = __floats2bfloat162_rn(b.z, b.w);
    uint4 r;
    r.x = *reinterpret_cast<unsigned*>(&p0);
    r.y = *reinterpret_cast<unsigned*>(&p1);
    r.z = *reinterpret_cast<unsigned*>(&p2);
    r.w = *reinterpret_cast<unsigned*>(&p3);
    return r;
}

// 128x128 block, warp tile 32x64 (8 warps)
__device__ __forceinline__ void mma_tile(const __nv_bfloat16* As, const __nv_bfloat16* Bs,
                                         FragC (&acc)[2][4], int wm, int wn) {
#pragma unroll
    for (int kk = 0; kk < BK; kk += 16) {
        FragA a[2];
        FragB b[4];
#pragma unroll
        for (int i = 0; i < 2; i++)
            wmma::load_matrix_sync(a[i], As + (wm * 32 + i * 16) * LDA_S + kk, LDA_S);
#pragma unroll
        for (int j = 0; j < 4; j++)
            wmma::load_matrix_sync(b[j], Bs + kk * LDB_S + wn * 64 + j * 16, LDB_S);
#pragma unroll
        for (int i = 0; i < 2; i++)
#pragma unroll
            for (int j = 0; j < 4; j++)
                wmma::mma_sync(acc[i][j], a[i], b[j], acc[i][j]);
    }
}

// raw PTX mma/ldmatrix for attention
__device__ __forceinline__ void mma16816(float c[4], const unsigned a[4],
                                         unsigned b0, unsigned b1) {
    asm volatile(
        "mma.sync.aligned.m16n8k16.row.col.f32.bf16.bf16.f32 "
        "{%0,%1,%2,%3}, {%4,%5,%6,%7}, {%8,%9}, {%0,%1,%2,%3};\n"
        : "+f"(c[0]), "+f"(c[1]), "+f"(c[2]), "+f"(c[3])
        : "r"(a[0]), "r"(a[1]), "r"(a[2]), "r"(a[3]), "r"(b0), "r"(b1));
}
__device__ __forceinline__ void ldsm4(unsigned d[4], unsigned addr) {
    asm volatile("ldmatrix.sync.aligned.m8n8.x4.shared.b16 {%0,%1,%2,%3}, [%4];\n"
        : "=r"(d[0]), "=r"(d[1]), "=r"(d[2]), "=r"(d[3]) : "r"(addr));
}
__device__ __forceinline__ void ldsm4t(unsigned d[4], unsigned addr) {
    asm volatile("ldmatrix.sync.aligned.m8n8.x4.trans.shared.b16 {%0,%1,%2,%3}, [%4];\n"
        : "=r"(d[0]), "=r"(d[1]), "=r"(d[2]), "=r"(d[3]) : "r"(addr));
}

// ---------------------------------------------------------------------------
// RMSNorm
// ---------------------------------------------------------------------------
__global__ void k_rmsnorm(const float* __restrict__ in,
                          const float* __restrict__ w,
                          float* __restrict__ outf,
                          __nv_bfloat16* __restrict__ outb) {
    int t = blockIdx.x;
    const float* x = in + (size_t)t * HID;
    float ss = 0.f;
    for (int i = threadIdx.x; i < HID; i += 256) { float v = x[i]; ss += v * v; }
#pragma unroll
    for (int o = 16; o; o >>= 1) ss += __shfl_xor_sync(0xffffffffu, ss, o);
    __shared__ float red[8];
    __shared__ float stot;
    if ((threadIdx.x & 31) == 0) red[threadIdx.x >> 5] = ss;
    __syncthreads();
    if (threadIdx.x == 0) {
        float s = 0.f;
#pragma unroll
        for (int i = 0; i < 8; i++) s += red[i];
        stot = rsqrtf(s * (1.f / HID) + 1e-6f);
    }
    __syncthreads();
    float sc = stot;
    for (int i = threadIdx.x; i < HID; i += 256) {
        float v = x[i] * sc * w[i];
        if (outf) outf[(size_t)t * HID + i] = v;
        if (outb) outb[(size_t)t * HID + i] = __float2bfloat16(v);
    }
}

// ---------------------------------------------------------------------------
// Dense bf16 GEMM (round-6 version: single reg prefetch, double smem buffer)
// ---------------------------------------------------------------------------
__global__ void __launch_bounds__(256) k_gemm_bf16(
        const __nv_bfloat16* __restrict__ A, const float* __restrict__ B,
        float* __restrict__ C, const float* __restrict__ R,
        int M, int N, int K) {
    __shared__ __nv_bfloat16 As[2][BM * LDA_S];
    __shared__ __nv_bfloat16 Bs[2][BK * LDB_S];
    int tid = threadIdx.x;
    int warp = tid >> 5;
    int wm = warp & 3, wn = warp >> 2;
    int m0 = blockIdx.y * BM, n0 = blockIdx.x * BN;

    int a_r = tid >> 2, a_c = (tid & 3) * 8;
    int b_r = tid >> 4, b_c = (tid & 15) * 8;

    FragC acc[2][4];
    if (R) {
#pragma unroll
        for (int i = 0; i < 2; i++)
#pragma unroll
            for (int j = 0; j < 4; j++)
                wmma::load_matrix_sync(acc[i][j],
                    R + (size_t)(m0 + wm * 32 + i * 16) * N + n0 + wn * 64 + j * 16,
                    N, wmma::mem_row_major);
    } else {
#pragma unroll
        for (int i = 0; i < 2; i++)
#pragma unroll
            for (int j = 0; j < 4; j++) wmma::fill_fragment(acc[i][j], 0.f);
    }

    uint4 ra0, ra1;
    float4 rb0a, rb0b, rb1a, rb1b;
    auto ldg = [&](int k0) {
        ra0 = *(const uint4*)&A[(size_t)(m0 + a_r) * K + k0 + a_c];
        ra1 = *(const uint4*)&A[(size_t)(m0 + a_r + 64) * K + k0 + a_c];
        const float* p0 = &B[(size_t)(k0 + b_r) * N + n0 + b_c];
        rb0a = *(const float4*)p0; rb0b = *(const float4*)(p0 + 4);
        const float* p1 = &B[(size_t)(k0 + b_r + 16) * N + n0 + b_c];
        rb1a = *(const float4*)p1; rb1b = *(const float4*)(p1 + 4);
    };
    auto sts = [&](int buf) {
        *(uint4*)&As[buf][a_r * LDA_S + a_c] = ra0;
        *(uint4*)&As[buf][(a_r + 64) * LDA_S + a_c] = ra1;
        *(uint4*)&Bs[buf][b_r * LDB_S + b_c] = f8_to_bf8(rb0a, rb0b);
        *(uint4*)&Bs[buf][(b_r + 16) * LDB_S + b_c] = f8_to_bf8(rb1a, rb1b);
    };

    int niter = K / BK;
    ldg(0); sts(0); __syncthreads();
    for (int it = 0; it < niter; it++) {
        if (it + 1 < niter) ldg((it + 1) * BK);
        mma_tile(As[it & 1], Bs[it & 1], acc, wm, wn);
        if (it + 1 < niter) { sts((it + 1) & 1); __syncthreads(); }
    }
#pragma unroll
    for (int i = 0; i < 2; i++)
#pragma unroll
        for (int j = 0; j < 4; j++)
            wmma::store_matrix_sync(
                C + (size_t)(m0 + wm * 32 + i * 16) * N + n0 + wn * 64 + j * 16,
                acc[i][j], N, wmma::mem_row_major);
}

// ---------------------------------------------------------------------------
// Per-head RMSNorm + RoPE (q,k) and copy (v) -> bf16.
// Batched: one block per token, 24 warps = 24 head-slots.
// ---------------------------------------------------------------------------
__global__ void __launch_bounds__(768) k_qk_prep(const int* __restrict__ pos,
                                                 const float* __restrict__ qnw,
                                                 const float* __restrict__ knw) {
    int t  = blockIdx.x;
    int hh = threadIdx.y;      // 0..23 (one warp per head-slot)
    int i  = threadIdx.x;      // 0..31
    if (hh >= NH + NKV) {      // v: plain copy to bf16
        int vh = hh - NH - NKV;
        const float* src = g_qkv + (size_t)t * QKV_N + (NH + NKV) * HD + vh * HD;
        __nv_bfloat16* dst = g_vb + (size_t)t * (NKV * HD) + vh * HD;
        dst[i]      = __float2bfloat16(src[i]);
        dst[i + 32] = __float2bfloat16(src[i + 32]);
        return;
    }
    const float* src; __nv_bfloat16* dst; const float* w;
    if (hh < NH) {
        src = g_qkv + (size_t)t * QKV_N + hh * HD;
        dst = g_qb  + (size_t)t * (NH * HD) + hh * HD;
        w = qnw;
    } else {
        int kh = hh - NH;
        src = g_qkv + (size_t)t * QKV_N + NH * HD + kh * HD;
        dst = g_kb  + (size_t)t * (NKV * HD) + kh * HD;
        w = knw;
    }
    float x1 = src[i], x2 = src[i + 32];
    float ss = x1 * x1 + x2 * x2;
#pragma unroll
    for (int o = 16; o; o >>= 1) ss += __shfl_xor_sync(0xffffffffu, ss, o);
    float sc = rsqrtf(ss * (1.f / 64.f) + 1e-6f);
    x1 *= sc * w[i];
    x2 *= sc * w[i + 32];
    float p = (float)pos[t];
    float inv = powf(10000.f, -(float)i * (1.f / 32.f));
    float f = p * inv;
    float c = cosf(f), s = sinf(f);
    dst[i]      = __float2bfloat16(x1 * c - x2 * s);
    dst[i + 32] = __float2bfloat16(x2 * c + x1 * s);
}

// ---------------------------------------------------------------------------
// Flash attention (round-6 register-resident FA2, unchanged)
// ---------------------------------------------------------------------------
__global__ void __launch_bounds__(128) k_attn_mma() {
    __shared__ __nv_bfloat16 Qs[64 * LDH];
    __shared__ __nv_bfloat16 Ks[64 * LDH];
    __shared__ __nv_bfloat16 Vs[64 * LDH];
    int h = blockIdx.y, qt = blockIdx.x;
    int m0 = qt * 64, kvh = h >> 2;
    int tid = threadIdx.x, warp = tid >> 5, lane = tid & 31;
    int g = lane >> 3, li = lane & 7;

#pragma unroll
    for (int j = 0; j < 4; j++) {
        int idx = tid + j * 128;
        int r = idx >> 3, c = (idx & 7) * 8;
        *(uint4*)&Qs[r * LDH + c] =
            *(const uint4*)&g_qb[(size_t)(m0 + r) * (NH * HD) + h * HD + c];
    }
    __syncthreads();

    unsigned qa[4][4];
    {
        int row = warp * 16 + (g & 1) * 8 + li;
        int colg = (g >> 1) * 8;
#pragma unroll
        for (int hc = 0; hc < 4; hc++)
            ldsm4(qa[hc], (unsigned)__cvta_generic_to_shared(&Qs[row * LDH + hc * 16 + colg]));
    }

    float o[8][4];
#pragma unroll
    for (int f = 0; f < 8; f++) { o[f][0] = o[f][1] = o[f][2] = o[f][3] = 0.f; }
    float mr0 = -INFINITY, mr1 = -INFINITY, l0 = 0.f, l1 = 0.f;
    int R0 = m0 + warp * 16 + (lane >> 2);
    int R1 = R0 + 8;

    for (int nt = 0; nt <= qt; nt++) {
        int n0 = nt * 64;
        __syncthreads();
#pragma unroll
        for (int j = 0; j < 4; j++) {
            int idx = tid + j * 128;
            int r = idx >> 3, c = (idx & 7) * 8;
            *(uint4*)&Ks[r * LDH + c] =
                *(const uint4*)&g_kb[(size_t)(n0 + r) * (NKV * HD) + kvh * HD + c];
            *(uint4*)&Vs[r * LDH + c] =
                *(const uint4*)&g_vb[(size_t)(n0 + r) * (NKV * HD) + kvh * HD + c];
        }
        __syncthreads();

        float s[8][4];
#pragma unroll
        for (int f = 0; f < 8; f++) { s[f][0] = s[f][1] = s[f][2] = s[f][3] = 0.f; }
#pragma unroll
        for (int hc = 0; hc < 4; hc++) {
#pragma unroll
            for (int ng = 0; ng < 4; ng++) {
                unsigned d[4];
                int row = ng * 16 + (g >> 1) * 8 + li;
                int col = hc * 16 + (g & 1) * 8;
                ldsm4(d, (unsigned)__cvta_generic_to_shared(&Ks[row * LDH + col]));
                mma16816(s[2 * ng],     qa[hc], d[0], d[1]);
                mma16816(s[2 * ng + 1], qa[hc], d[2], d[3]);
            }
        }

        bool diag = (nt == qt);
        float mx0 = -INFINITY, mx1 = -INFINITY;
#pragma unroll
        for (int f = 0; f < 8; f++) {
            int cb = n0 + f * 8 + (lane & 3) * 2;
            s[f][0] *= 0.125f; s[f][1] *= 0.125f;
            s[f][2] *= 0.125f; s[f][3] *= 0.125f;
            if (diag) {
                if (cb     > R0) s[f][0] = -INFINITY;
                if (cb + 1 > R0) s[f][1] = -INFINITY;
                if (cb     > R1) s[f][2] = -INFINITY;
                if (cb + 1 > R1) s[f][3] = -INFINITY;
            }
            mx0 = fmaxf(mx0, fmaxf(s[f][0], s[f][1]));
            mx1 = fmaxf(mx1, fmaxf(s[f][2], s[f][3]));
        }
        mx0 = fmaxf(mx0, __shfl_xor_sync(0xffffffffu, mx0, 1));
        mx0 = fmaxf(mx0, __shfl_xor_sync(0xffffffffu, mx0, 2));
        mx1 = fmaxf(mx1, __shfl_xor_sync(0xffffffffu, mx1, 1));
        mx1 = fmaxf(mx1, __shfl_xor_sync(0xffffffffu, mx1, 2));
        float mn0 = fmaxf(mr0, mx0), mn1 = fmaxf(mr1, mx1);
        float al0 = __expf(mr0 - mn0), al1 = __expf(mr1 - mn1);
        mr0 = mn0; mr1 = mn1;

        unsigned P[4][4];
        float ps0 = 0.f, ps1 = 0.f;
#pragma unroll
        for (int f = 0; f < 8; f++) {
            float p0 = __expf(s[f][0] - mn0);
            float p1 = __expf(s[f][1] - mn0);
            float p2 = __expf(s[f][2] - mn1);
            float p3 = __expf(s[f][3] - mn1);
            ps0 += p0 + p1; ps1 += p2 + p3;
            __nv_bfloat162 b0 = __floats2bfloat162_rn(p0, p1);
            __nv_bfloat162 b1 = __floats2bfloat162_rn(p2, p3);
            P[f >> 1][(f & 1) * 2]     = *reinterpret_cast<unsigned*>(&b0);
            P[f >> 1][(f & 1) * 2 + 1] = *reinterpret_cast<unsigned*>(&b1);
        }
        ps0 += __shfl_xor_sync(0xffffffffu, ps0, 1);
        ps0 += __shfl_xor_sync(0xffffffffu, ps0, 2);
        ps1 += __shfl_xor_sync(0xffffffffu, ps1, 1);
        ps1 += __shfl_xor_sync(0xffffffffu, ps1, 2);
        l0 = l0 * al0 + ps0;
        l1 = l1 * al1 + ps1;
#pragma unroll
        for (int f = 0; f < 8; f++) {
            o[f][0] *= al0; o[f][1] *= al0;
            o[f][2] *= al1; o[f][3] *= al1;
        }

#pragma unroll
        for (int c = 0; c < 4; c++) {
#pragma unroll
            for (int j = 0; j < 4; j++) {
                unsigned d[4];
                int row = c * 16 + (g & 1) * 8 + li;
                int col = j * 16 + (g >> 1) * 8;
                ldsm4t(d, (unsigned)__cvta_generic_to_shared(&Vs[row * LDH + col]));
                mma16816(o[2 * j],     P[c], d[0], d[1]);
                mma16816(o[2 * j + 1], P[c], d[2], d[3]);
            }
        }
    }

    float i0 = 1.f / l0, i1 = 1.f / l1;
#pragma unroll
    for (int f = 0; f < 8; f++) {
        int col = h * HD + f * 8 + (lane & 3) * 2;
        __nv_bfloat162 v0 = __floats2bfloat162_rn(o[f][0] * i0, o[f][1] * i0);
        __nv_bfloat162 v1 = __floats2bfloat162_rn(o[f][2] * i1, o[f][3] * i1);
        *(unsigned*)&g_attnb[(size_t)R0 * (NH * HD) + col] = *reinterpret_cast<unsigned*>(&v0);
        *(unsigned*)&g_attnb[(size_t)R1 * (NH * HD) + col] = *reinterpret_cast<unsigned*>(&v1);
    }
}

// ---------------------------------------------------------------------------
// Routing
// ---------------------------------------------------------------------------
__global__ void k_zero() {
    int i = threadIdx.x;
    if (i < NE) { g_cnt[i] = 0; g_fill[i] = 0; }
}

__global__ void k_route(const float* __restrict__ H2, const float* __restrict__ Wg) {
    int t = blockIdx.x;
    int e = threadIdx.x;
    __shared__ float sh[HID];
    for (int i = e; i < HID; i += 64) sh[i] = H2[(size_t)t * HID + i];
    __syncthreads();
    float a0 = 0, a1 = 0, a2 = 0, a3 = 0;
    for (int k = 0; k < HID; k += 4) {
        a0 += sh[k]     * Wg[(size_t)k       * NE + e];
        a1 += sh[k + 1] * Wg[(size_t)(k + 1) * NE + e];
        a2 += sh[k + 2] * Wg[(size_t)(k + 2) * NE + e];
        a3 += sh[k + 3] * Wg[(size_t)(k + 3) * NE + e];
    }
    __shared__ float logits[NE];
    logits[e] = (a0 + a1) + (a2 + a3);
    __syncthreads();
    if (e == 0) {
        float sv[NG]; int si[NG];
#pragma unroll
        for (int gg = 0; gg < NG; gg++) {
            float best = logits[gg * 8]; int bi = gg * 8;
#pragma unroll
            for (int j = 1; j < 8; j++) {
                float v = logits[gg * 8 + j];
                if (v > best) { best = v; bi = gg * 8 + j; }
            }
            sv[gg] = best; si[gg] = bi;
        }
        float m = sv[0];
#pragma unroll
        for (int gg = 1; gg < NG; gg++) m = fmaxf(m, sv[gg]);
        float sum = 0.f, p[NG];
#pragma unroll
        for (int gg = 0; gg < NG; gg++) { p[gg] = expf(sv[gg] - m); sum += p[gg]; }
        float is = 1.f / sum;
#pragma unroll
        for (int gg = 0; gg < NG; gg++) {
            g_selid[t * NG + gg] = si[gg];
            g_selw [t * NG + gg] = p[gg] * is;
            atomicAdd(&g_cnt[si[gg]], 1);
        }
    }
}

__global__ void k_scan() {  // pad to 128 (MoE BM)
    int s = 0;
    for (int e = 0; e < NE; e++) { g_off[e] = s; s += (g_cnt[e] + BM - 1) & ~(BM - 1); }
    g_total = s;
}

__global__ void k_scatter() {
    int t = blockIdx.x, gg = threadIdx.x;
    int e = g_selid[t * NG + gg];
    int slot = atomicAdd(&g_fill[e], 1);
    int row = g_off[e] + slot;
    g_tok[row] = t;
    g_w[row]   = g_selw[t * NG + gg];
}

// ---------------------------------------------------------------------------
// MoE GEMM 1: BM=128, BN=128 (64 gate + 64 up cols). A via cp.async,
// B via LDG + in-loop fp32->bf16 convert. Fused silu epilogue.
// ---------------------------------------------------------------------------
#define MOE1_SMEM 67584   // max(pipeline 37888, epilogue 128*132*4)
__global__ void __launch_bounds__(256) k_moe1(const __nv_bfloat16* __restrict__ Ab,
                                              const float* __restrict__ Wgu) {
    extern __shared__ __align__(16) char dyn1[];
    __shared__ int stok[BM];
    __nv_bfloat16* As = (__nv_bfloat16*)dyn1;                    // 2 x BM*LDA_S
    __nv_bfloat16* Bs = (__nv_bfloat16*)(dyn1 + 2 * BM * LDA_S * 2);
    float* Ebuf = (float*)dyn1;                                  // epilogue alias

    int e = blockIdx.z;
    int cnt = g_cnt[e];
    int m0 = blockIdx.y * BM;
    if (m0 >= cnt) return;
    int off = g_off[e];
    int n0 = blockIdx.x * 64;
    const float* B = Wgu + (size_t)e * (HID * 1024);

    int tid = threadIdx.x;
    int warp = tid >> 5;
    int wm = warp & 3, wn = warp >> 2;
    if (tid < BM) stok[tid] = (m0 + tid < cnt) ? g_tok[off + m0 + tid] : -1;
    __syncthreads();

    int a_r = tid >> 2, a_c = (tid & 3) * 8;
    int b_r = tid >> 4, b_c = (tid & 15) * 8;
    int tk0 = stok[a_r], tk1 = stok[a_r + 64];
    const __nv_bfloat16* a0 = Ab + (size_t)((tk0 >= 0) ? tk0 : 0) * HID + a_c;
    const __nv_bfloat16* a1 = Ab + (size_t)((tk1 >= 0) ? tk1 : 0) * HID + a_c;
    int colg = (b_c < 64) ? (n0 + b_c) : (512 + n0 + b_c - 64);
    unsigned dA0 = (unsigned)__cvta_generic_to_shared(&As[a_r * LDA_S + a_c]);
    unsigned dA1 = (unsigned)__cvta_generic_to_shared(&As[(a_r + 64) * LDA_S + a_c]);
    const unsigned szA = BM * LDA_S * 2;

    FragC acc[2][4];
#pragma unroll
    for (int i = 0; i < 2; i++)
#pragma unroll
        for (int j = 0; j < 4; j++) wmma::fill_fragment(acc[i][j], 0.f);

    float4 rb0a, rb0b, rb1a, rb1b;
    auto cpA = [&](int buf, int k0) {
        cp16z(dA0 + buf * szA, a0 + k0, tk0 >= 0);
        cp16z(dA1 + buf * szA, a1 + k0, tk1 >= 0);
        CP_COMMIT();
    };
    auto ldgB = [&](int k0) {
        const float* p0 = &B[(size_t)(k0 + b_r) * 1024 + colg];
        rb0a = *(const float4*)p0; rb0b = *(const float4*)(p0 + 4);
        const float* p1 = &B[(size_t)(k0 + b_r + 16) * 1024 + colg];
        rb1a = *(const float4*)p1; rb1b = *(const float4*)(p1 + 4);
    };
    auto stsB = [&](int buf) {
        *(uint4*)&Bs[buf * BK * LDB_S + b_r * LDB_S + b_c] = f8_to_bf8(rb0a, rb0b);
        *(uint4*)&Bs[buf * BK * LDB_S + (b_r + 16) * LDB_S + b_c] = f8_to_bf8(rb1a, rb1b);
    };

    const int niter = HID / BK;
    cpA(0, 0); ldgB(0); stsB(0);
    cp_wait<0>(); __syncthreads();
    for (int it = 0; it < niter; it++) {
        if (it + 1 < niter) { cpA((it + 1) & 1, (it + 1) * BK); ldgB((it + 1) * BK); }
        mma_tile(As + (it & 1) * BM * LDA_S, Bs + (it & 1) * BK * LDB_S, acc, wm, wn);
        if (it + 1 < niter) { stsB((it + 1) & 1); cp_wait<0>(); __syncthreads(); }
    }

    // ---- fused activation epilogue ----
    __syncthreads();   // all warps done reading pipeline smem before alias reuse
#pragma unroll
    for (int i = 0; i < 2; i++)
#pragma unroll
        for (int j = 0; j < 4; j++)
            wmma::store_matrix_sync(Ebuf + (wm * 32 + i * 16) * 132 + wn * 64 + j * 16,
                                    acc[i][j], 132, wmma::mem_row_major);
    __syncthreads();

    int r  = tid >> 1;
    int c0 = (tid & 1) * 32;
    float wt = (m0 + r < cnt) ? g_w[off + m0 + r] : 0.f;
    unsigned vals[16];
#pragma unroll
    for (int q = 0; q < 16; q++) {
        float g0 = Ebuf[r * 132 + c0 + q * 2];
        float g1 = Ebuf[r * 132 + c0 + q * 2 + 1];
        float u0 = Ebuf[r * 132 + 64 + c0 + q * 2];
        float u1 = Ebuf[r * 132 + 64 + c0 + q * 2 + 1];
        float x0 = g0 / (1.f + __expf(-g0)) * u0 * wt;
        float x1 = g1 / (1.f + __expf(-g1)) * u1 * wt;
        __nv_bfloat162 p = __floats2bfloat162_rn(x0, x1);
        vals[q] = *reinterpret_cast<unsigned*>(&p);
    }
    uint4* dst = (uint4*)&g_actb[(size_t)(off + m0 + r) * INTER + n0 + c0];
#pragma unroll
    for (int q = 0; q < 4; q++)
        dst[q] = make_uint4(vals[q * 4], vals[q * 4 + 1], vals[q * 4 + 2], vals[q * 4 + 3]);
}

// ---------------------------------------------------------------------------
// MoE GEMM 2: BM=128, A via cp.async, staged atomic scatter-add.
// ---------------------------------------------------------------------------
__global__ void __launch_bounds__(256) k_moe2(const float* __restrict__ Wd,
                                              float* __restrict__ out) {
    int e = blockIdx.z;
    int cnt = g_cnt[e];
    int m0 = blockIdx.y * BM;
    if (m0 >= cnt) return;
    int off = g_off[e];
    int n0 = blockIdx.x * BN;
    const float* B = Wd + (size_t)e * (INTER * HID);

    __shared__ __nv_bfloat16 As[2][BM * LDA_S];
    __shared__ __nv_bfloat16 Bs[2][BK * LDB_S];
    __shared__ float stage_s[8 * 272];
    __shared__ int stok[BM];
    int tid = threadIdx.x;
    int lane = tid & 31;
    int warp = tid >> 5;
    int wm = warp & 3, wn = warp >> 2;
    if (tid < BM) stok[tid] = (m0 + tid < cnt) ? g_tok[off + m0 + tid] : -1;
    __syncthreads();

    int a_r = tid >> 2, a_c = (tid & 3) * 8;
    int b_r = tid >> 4, b_c = (tid & 15) * 8;
    const __nv_bfloat16* a0 = g_actb + (size_t)(off + m0 + a_r) * INTER + a_c;
    const __nv_bfloat16* a1 = g_actb + (size_t)(off + m0 + a_r + 64) * INTER + a_c;
    unsigned dA0 = (unsigned)__cvta_generic_to_shared(&As[0][a_r * LDA_S + a_c]);
    unsigned dA1 = (unsigned)__cvta_generic_to_shared(&As[0][(a_r + 64) * LDA_S + a_c]);
    const unsigned szA = BM * LDA_S * 2;

    FragC acc[2][4];
#pragma unroll
    for (int i = 0; i < 2; i++)
#pragma unroll
        for (int j = 0; j < 4; j++) wmma::fill_fragment(acc[i][j], 0.f);

    float4 rb0a, rb0b, rb1a, rb1b;
    auto cpA = [&](int buf, int k0) {
        // padding rows of g_actb hold zeros (moe1 wrote them with wt=0)
        cp16(dA0 + buf * szA, a0 + k0);
        cp16(dA1 + buf * szA, a1 + k0);
        CP_COMMIT();
    };
    auto ldgB = [&](int k0) {
        const float* p0 = &B[(size_t)(k0 + b_r) * HID + n0 + b_c];
        rb0a = *(const float4*)p0; rb0b = *(const float4*)(p0 + 4);
        const float* p1 = &B[(size_t)(k0 + b_r + 16) * HID + n0 + b_c];
        rb1a = *(const float4*)p1; rb1b = *(const float4*)(p1 + 4);
    };
    auto stsB = [&](int buf) {
        *(uint4*)&Bs[buf][b_r * LDB_S + b_c] = f8_to_bf8(rb0a, rb0b);
        *(uint4*)&Bs[buf][(b_r + 16) * LDB_S + b_c] = f8_to_bf8(rb1a, rb1b);
    };

    const int niter = INTER / BK;
    cpA(0, 0); ldgB(0); stsB(0);
    cp_wait<0>(); __syncthreads();
    for (int it = 0; it < niter; it++) {
        if (it + 1 < niter) { cpA((it + 1) & 1, (it + 1) * BK); ldgB((it + 1) * BK); }
        mma_tile(As[it & 1], Bs[it & 1], acc, wm, wn);
        if (it + 1 < niter) { stsB((it + 1) & 1); cp_wait<0>(); __syncthreads(); }
    }

#pragma unroll
    for (int i = 0; i < 2; i++) {
#pragma unroll
        for (int j = 0; j < 4; j++) {
            wmma::store_matrix_sync(&stage_s[warp * 272], acc[i][j], 16, wmma::mem_row_major);
            __syncwarp();
#pragma unroll
            for (int q = 0; q < 8; q++) {
                int el = lane + q * 32;
                int r = el >> 4, c = el & 15;
                int lr = wm * 32 + i * 16 + r;
                if (m0 + lr < cnt) {
                    int tk = stok[lr];
                    atomicAdd(&out[(size_t)tk * HID + n0 + wn * 64 + j * 16 + c],
                              stage_s[warp * 272 + r * 16 + c]);
                }
            }
            __syncwarp();
        }
    }
}

// ---------------------------------------------------------------------------
// Launch
// ---------------------------------------------------------------------------
extern "C" void kernel_launch(void* const* d_in, const int* in_sizes, int n_in,
                              void* d_out, int out_size) {
    const int*   positions = (const int*)  d_in[0];
    const float* hidden    = (const float*)d_in[1];
    const float* Wqkv      = (const float*)d_in[2];
    const float* Wo        = (const float*)d_in[3];
    const float* qnw       = (const float*)d_in[4];
    const float* knw       = (const float*)d_in[5];
    const float* inln      = (const float*)d_in[6];
    const float* postln    = (const float*)d_in[7];
    const float* Wg        = (const float*)d_in[8];
    const float* Wgu       = (const float*)d_in[9];
    const float* Wd        = (const float*)d_in[10];
    float* out = (float*)d_out;

    __nv_bfloat16 *p_hb, *p_attnb, *p_h2b;
    float *p_qkv, *p_h2;
    cudaGetSymbolAddress((void**)&p_hb,    g_hb);
    cudaGetSymbolAddress((void**)&p_qkv,   g_qkv);
    cudaGetSymbolAddress((void**)&p_h2,    g_h2);
    cudaGetSymbolAddress((void**)&p_h2b,   g_h2b);
    cudaGetSymbolAddress((void**)&p_attnb, g_attnb);

    cudaFuncSetAttribute(k_moe1, cudaFuncAttributeMaxDynamicSharedMemorySize, MOE1_SMEM);

    k_rmsnorm<<<T_TOK, 256>>>(hidden, inln, nullptr, p_hb);
    k_gemm_bf16<<<dim3(QKV_N / BN, T_TOK / BM), 256>>>(p_hb, Wqkv, p_qkv, nullptr,
                                                       T_TOK, QKV_N, HID);
    k_qk_prep<<<T_TOK, dim3(32, NH + 2 * NKV)>>>(positions, qnw, knw);
    k_attn_mma<<<dim3(T_TOK / 64, NH), 128>>>();
    k_gemm_bf16<<<dim3(HID / BN, T_TOK / BM), 256>>>(p_attnb, Wo, out, hidden,
                                                     T_TOK, HID, NH * HD);
    k_rmsnorm<<<T_TOK, 256>>>(out, postln, p_h2, p_h2b);
    k_zero<<<1, 64>>>();
    k_route<<<T_TOK, 64>>>(p_h2, Wg);
    k_scan<<<1, 1>>>();
    k_scatter<<<T_TOK, 8>>>();
    // grouped gate_up GEMM (A cp.async) + fused activation
    k_moe1<<<dim3(8, 8, NE), 256, MOE1_SMEM>>>(p_h2b, Wgu);
    // grouped down GEMM (A cp.async), scatter-add into d_out
    k_moe2<<<dim3(HID / BN, 8, NE), 256>>>(Wd, out);
}

// round 17
// speedup vs baseline: 1.1008x; 1.0049x over previous
#include <cuda_runtime.h>
#include <cuda_bf16.h>
#include <mma.h>
#include <math.h>

using namespace nvcuda;

// ---------------------------------------------------------------------------
// Problem constants
// ---------------------------------------------------------------------------
#define T_TOK  1024
#define HID    1024
#define NH     16
#define NKV    4
#define HD     64
#define QKV_N  1536
#define NE     64
#define NG     8
#define INTER  512
#define NA     (T_TOK*NG)
#define NA_PAD 16384

// GEMM tiling
#define BM 128
#define BN 128
#define BK 32
#define LDA_S 40
#define LDB_S 136

// attention smem leading dim
#define LDH 72

// ---------------------------------------------------------------------------
// Scratch (static device globals)
// ---------------------------------------------------------------------------
__device__ __nv_bfloat16 g_hb   [T_TOK*HID];
__device__ float         g_qkv  [T_TOK*QKV_N];
__device__ __nv_bfloat16 g_qb   [T_TOK*NH*HD];
__device__ __nv_bfloat16 g_kb   [T_TOK*NKV*HD];
__device__ __nv_bfloat16 g_vb   [T_TOK*NKV*HD];
__device__ __nv_bfloat16 g_attnb[T_TOK*NH*HD];
__device__ float         g_h2   [T_TOK*HID];
__device__ __nv_bfloat16 g_h2b  [T_TOK*HID];
__device__ __nv_bfloat16 g_actb [NA_PAD*INTER];
__device__ int   g_cnt [NE];
__device__ int   g_off [NE];
__device__ int   g_fill[NE];
__device__ int   g_total;
__device__ int   g_selid[NA];
__device__ float g_selw [NA];
__device__ int   g_tok  [NA_PAD];
__device__ float g_w    [NA_PAD];

// ---------------------------------------------------------------------------
// WMMA types + helpers
// ---------------------------------------------------------------------------
using FragA  = wmma::fragment<wmma::matrix_a, 16, 16, 16, __nv_bfloat16, wmma::row_major>;
using FragB  = wmma::fragment<wmma::matrix_b, 16, 16, 16, __nv_bfloat16, wmma::row_major>;
using FragC  = wmma::fragment<wmma::accumulator, 16, 16, 16, float>;

__device__ __forceinline__ void cp16(unsigned dst, const void* src) {
    asm volatile("cp.async.cg.shared.global [%0], [%1], 16;\n" :: "r"(dst), "l"(src));
}
__device__ __forceinline__ void cp16z(unsigned dst, const void* src, int valid) {
    asm volatile("cp.async.cg.shared.global [%0], [%1], 16, %2;\n"
                 :: "r"(dst), "l"(src), "r"(valid ? 16 : 0));
}
#define CP_COMMIT() asm volatile("cp.async.commit_group;\n")
template<int N> __device__ __forceinline__ void cp_wait() {
    asm volatile("cp.async.wait_group %0;\n" :: "n"(N));
}

__device__ __forceinline__ uint4 f8_to_bf8(float4 a, float4 b) {
    __nv_bfloat162 p0 = __floats2bfloat162_rn(a.x, a.y);
    __nv_bfloat162 p1 = __floats2bfloat162_rn(a.z, a.w);
    __nv_bfloat162 p2 = __floats2bfloat162_rn(b.x, b.y);
    __nv_bfloat162 p3 = __floats2bfloat162_rn(b.z, b.w);
    uint4 r;
    r.x = *reinterpret_cast<unsigned*>(&p0);
    r.y = *reinterpret_cast<unsigned*>(&p1);
    r.z = *reinterpret_cast<unsigned*>(&p2);
    r.w = *reinterpret_cast<unsigned*>(&p3);
    return r;
}

// 128x128 block, warp tile 32x64 (8 warps)
__device__ __forceinline__ void mma_tile(const __nv_bfloat16* As, const __nv_bfloat16* Bs,
                                         FragC (&acc)[2][4], int wm, int wn) {
#pragma unroll
    for (int kk = 0; kk < BK; kk += 16) {
        FragA a[2];
        FragB b[4];
#pragma unroll
        for (int i = 0; i < 2; i++)
            wmma::load_matrix_sync(a[i], As + (wm * 32 + i * 16) * LDA_S + kk, LDA_S);
#pragma unroll
        for (int j = 0; j < 4; j++)
            wmma::load_matrix_sync(b[j], Bs + kk * LDB_S + wn * 64 + j * 16, LDB_S);
#pragma unroll
        for (int i = 0; i < 2; i++)
#pragma unroll
            for (int j = 0; j < 4; j++)
                wmma::mma_sync(acc[i][j], a[i], b[j], acc[i][j]);
    }
}

// raw PTX mma/ldmatrix for attention
__device__ __forceinline__ void mma16816(float c[4], const unsigned a[4],
                                         unsigned b0, unsigned b1) {
    asm volatile(
        "mma.sync.aligned.m16n8k16.row.col.f32.bf16.bf16.f32 "
        "{%0,%1,%2,%3}, {%4,%5,%6,%7}, {%8,%9}, {%0,%1,%2,%3};\n"
        : "+f"(c[0]), "+f"(c[1]), "+f"(c[2]), "+f"(c[3])
        : "r"(a[0]), "r"(a[1]), "r"(a[2]), "r"(a[3]), "r"(b0), "r"(b1));
}
__device__ __forceinline__ void ldsm4(unsigned d[4], unsigned addr) {
    asm volatile("ldmatrix.sync.aligned.m8n8.x4.shared.b16 {%0,%1,%2,%3}, [%4];\n"
        : "=r"(d[0]), "=r"(d[1]), "=r"(d[2]), "=r"(d[3]) : "r"(addr));
}
__device__ __forceinline__ void ldsm4t(unsigned d[4], unsigned addr) {
    asm volatile("ldmatrix.sync.aligned.m8n8.x4.trans.shared.b16 {%0,%1,%2,%3}, [%4];\n"
        : "=r"(d[0]), "=r"(d[1]), "=r"(d[2]), "=r"(d[3]) : "r"(addr));
}

// ---------------------------------------------------------------------------
// RMSNorm
// ---------------------------------------------------------------------------
__global__ void k_rmsnorm(const float* __restrict__ in,
                          const float* __restrict__ w,
                          float* __restrict__ outf,
                          __nv_bfloat16* __restrict__ outb) {
    int t = blockIdx.x;
    const float* x = in + (size_t)t * HID;
    float ss = 0.f;
    for (int i = threadIdx.x; i < HID; i += 256) { float v = x[i]; ss += v * v; }
#pragma unroll
    for (int o = 16; o; o >>= 1) ss += __shfl_xor_sync(0xffffffffu, ss, o);
    __shared__ float red[8];
    __shared__ float stot;
    if ((threadIdx.x & 31) == 0) red[threadIdx.x >> 5] = ss;
    __syncthreads();
    if (threadIdx.x == 0) {
        float s = 0.f;
#pragma unroll
        for (int i = 0; i < 8; i++) s += red[i];
        stot = rsqrtf(s * (1.f / HID) + 1e-6f);
    }
    __syncthreads();
    float sc = stot;
    for (int i = threadIdx.x; i < HID; i += 256) {
        float v = x[i] * sc * w[i];
        if (outf) outf[(size_t)t * HID + i] = v;
        if (outb) outb[(size_t)t * HID + i] = __float2bfloat16(v);
    }
}

// ---------------------------------------------------------------------------
// Dense bf16 GEMM: A via cp.async (bf16), B via LDG + in-loop convert.
// ---------------------------------------------------------------------------
__global__ void __launch_bounds__(256) k_gemm_bf16(
        const __nv_bfloat16* __restrict__ A, const float* __restrict__ B,
        float* __restrict__ C, const float* __restrict__ R,
        int M, int N, int K) {
    __shared__ __nv_bfloat16 As[2][BM * LDA_S];
    __shared__ __nv_bfloat16 Bs[2][BK * LDB_S];
    int tid = threadIdx.x;
    int warp = tid >> 5;
    int wm = warp & 3, wn = warp >> 2;
    int m0 = blockIdx.y * BM, n0 = blockIdx.x * BN;

    int a_r = tid >> 2, a_c = (tid & 3) * 8;
    int b_r = tid >> 4, b_c = (tid & 15) * 8;
    const __nv_bfloat16* a0 = A + (size_t)(m0 + a_r) * K + a_c;
    const __nv_bfloat16* a1 = A + (size_t)(m0 + a_r + 64) * K + a_c;
    unsigned dA0 = (unsigned)__cvta_generic_to_shared(&As[0][a_r * LDA_S + a_c]);
    unsigned dA1 = (unsigned)__cvta_generic_to_shared(&As[0][(a_r + 64) * LDA_S + a_c]);
    const unsigned szA = BM * LDA_S * 2;

    FragC acc[2][4];
    if (R) {
#pragma unroll
        for (int i = 0; i < 2; i++)
#pragma unroll
            for (int j = 0; j < 4; j++)
                wmma::load_matrix_sync(acc[i][j],
                    R + (size_t)(m0 + wm * 32 + i * 16) * N + n0 + wn * 64 + j * 16,
                    N, wmma::mem_row_major);
    } else {
#pragma unroll
        for (int i = 0; i < 2; i++)
#pragma unroll
            for (int j = 0; j < 4; j++) wmma::fill_fragment(acc[i][j], 0.f);
    }

    float4 rb0a, rb0b, rb1a, rb1b;
    auto cpA = [&](int buf, int k0) {
        cp16(dA0 + buf * szA, a0 + k0);
        cp16(dA1 + buf * szA, a1 + k0);
        CP_COMMIT();
    };
    auto ldgB = [&](int k0) {
        const float* p0 = &B[(size_t)(k0 + b_r) * N + n0 + b_c];
        rb0a = *(const float4*)p0; rb0b = *(const float4*)(p0 + 4);
        const float* p1 = &B[(size_t)(k0 + b_r + 16) * N + n0 + b_c];
        rb1a = *(const float4*)p1; rb1b = *(const float4*)(p1 + 4);
    };
    auto stsB = [&](int buf) {
        *(uint4*)&Bs[buf][b_r * LDB_S + b_c] = f8_to_bf8(rb0a, rb0b);
        *(uint4*)&Bs[buf][(b_r + 16) * LDB_S + b_c] = f8_to_bf8(rb1a, rb1b);
    };

    const int niter = K / BK;
    cpA(0, 0); ldgB(0); stsB(0);
    cp_wait<0>(); __syncthreads();
    for (int it = 0; it < niter; it++) {
        if (it + 1 < niter) { cpA((it + 1) & 1, (it + 1) * BK); ldgB((it + 1) * BK); }
        mma_tile(As[it & 1], Bs[it & 1], acc, wm, wn);
        if (it + 1 < niter) { stsB((it + 1) & 1); cp_wait<0>(); __syncthreads(); }
    }
#pragma unroll
    for (int i = 0; i < 2; i++)
#pragma unroll
        for (int j = 0; j < 4; j++)
            wmma::store_matrix_sync(
                C + (size_t)(m0 + wm * 32 + i * 16) * N + n0 + wn * 64 + j * 16,
                acc[i][j], N, wmma::mem_row_major);
}

// ---------------------------------------------------------------------------
// Per-head RMSNorm + RoPE (q,k) and copy (v) -> bf16.
// Batched: one block per token, 24 warps = 24 head-slots.
// ---------------------------------------------------------------------------
__global__ void __launch_bounds__(768) k_qk_prep(const int* __restrict__ pos,
                                                 const float* __restrict__ qnw,
                                                 const float* __restrict__ knw) {
    int t  = blockIdx.x;
    int hh = threadIdx.y;      // 0..23 (one warp per head-slot)
    int i  = threadIdx.x;      // 0..31
    if (hh >= NH + NKV) {      // v: plain copy to bf16
        int vh = hh - NH - NKV;
        const float* src = g_qkv + (size_t)t * QKV_N + (NH + NKV) * HD + vh * HD;
        __nv_bfloat16* dst = g_vb + (size_t)t * (NKV * HD) + vh * HD;
        dst[i]      = __float2bfloat16(src[i]);
        dst[i + 32] = __float2bfloat16(src[i + 32]);
        return;
    }
    const float* src; __nv_bfloat16* dst; const float* w;
    if (hh < NH) {
        src = g_qkv + (size_t)t * QKV_N + hh * HD;
        dst = g_qb  + (size_t)t * (NH * HD) + hh * HD;
        w = qnw;
    } else {
        int kh = hh - NH;
        src = g_qkv + (size_t)t * QKV_N + NH * HD + kh * HD;
        dst = g_kb  + (size_t)t * (NKV * HD) + kh * HD;
        w = knw;
    }
    float x1 = src[i], x2 = src[i + 32];
    float ss = x1 * x1 + x2 * x2;
#pragma unroll
    for (int o = 16; o; o >>= 1) ss += __shfl_xor_sync(0xffffffffu, ss, o);
    float sc = rsqrtf(ss * (1.f / 64.f) + 1e-6f);
    x1 *= sc * w[i];
    x2 *= sc * w[i + 32];
    float p = (float)pos[t];
    float inv = powf(10000.f, -(float)i * (1.f / 32.f));
    float f = p * inv;
    float c = cosf(f), s = sinf(f);
    dst[i]      = __float2bfloat16(x1 * c - x2 * s);
    dst[i + 32] = __float2bfloat16(x2 * c + x1 * s);
}

// ---------------------------------------------------------------------------
// Flash attention (register-resident FA2, unchanged)
// ---------------------------------------------------------------------------
__global__ void __launch_bounds__(128) k_attn_mma() {
    __shared__ __nv_bfloat16 Qs[64 * LDH];
    __shared__ __nv_bfloat16 Ks[64 * LDH];
    __shared__ __nv_bfloat16 Vs[64 * LDH];
    int h = blockIdx.y, qt = blockIdx.x;
    int m0 = qt * 64, kvh = h >> 2;
    int tid = threadIdx.x, warp = tid >> 5, lane = tid & 31;
    int g = lane >> 3, li = lane & 7;

#pragma unroll
    for (int j = 0; j < 4; j++) {
        int idx = tid + j * 128;
        int r = idx >> 3, c = (idx & 7) * 8;
        *(uint4*)&Qs[r * LDH + c] =
            *(const uint4*)&g_qb[(size_t)(m0 + r) * (NH * HD) + h * HD + c];
    }
    __syncthreads();

    unsigned qa[4][4];
    {
        int row = warp * 16 + (g & 1) * 8 + li;
        int colg = (g >> 1) * 8;
#pragma unroll
        for (int hc = 0; hc < 4; hc++)
            ldsm4(qa[hc], (unsigned)__cvta_generic_to_shared(&Qs[row * LDH + hc * 16 + colg]));
    }

    float o[8][4];
#pragma unroll
    for (int f = 0; f < 8; f++) { o[f][0] = o[f][1] = o[f][2] = o[f][3] = 0.f; }
    float mr0 = -INFINITY, mr1 = -INFINITY, l0 = 0.f, l1 = 0.f;
    int R0 = m0 + warp * 16 + (lane >> 2);
    int R1 = R0 + 8;

    for (int nt = 0; nt <= qt; nt++) {
        int n0 = nt * 64;
        __syncthreads();
#pragma unroll
        for (int j = 0; j < 4; j++) {
            int idx = tid + j * 128;
            int r = idx >> 3, c = (idx & 7) * 8;
            *(uint4*)&Ks[r * LDH + c] =
                *(const uint4*)&g_kb[(size_t)(n0 + r) * (NKV * HD) + kvh * HD + c];
            *(uint4*)&Vs[r * LDH + c] =
                *(const uint4*)&g_vb[(size_t)(n0 + r) * (NKV * HD) + kvh * HD + c];
        }
        __syncthreads();

        float s[8][4];
#pragma unroll
        for (int f = 0; f < 8; f++) { s[f][0] = s[f][1] = s[f][2] = s[f][3] = 0.f; }
#pragma unroll
        for (int hc = 0; hc < 4; hc++) {
#pragma unroll
            for (int ng = 0; ng < 4; ng++) {
                unsigned d[4];
                int row = ng * 16 + (g >> 1) * 8 + li;
                int col = hc * 16 + (g & 1) * 8;
                ldsm4(d, (unsigned)__cvta_generic_to_shared(&Ks[row * LDH + col]));
                mma16816(s[2 * ng],     qa[hc], d[0], d[1]);
                mma16816(s[2 * ng + 1], qa[hc], d[2], d[3]);
            }
        }

        bool diag = (nt == qt);
        float mx0 = -INFINITY, mx1 = -INFINITY;
#pragma unroll
        for (int f = 0; f < 8; f++) {
            int cb = n0 + f * 8 + (lane & 3) * 2;
            s[f][0] *= 0.125f; s[f][1] *= 0.125f;
            s[f][2] *= 0.125f; s[f][3] *= 0.125f;
            if (diag) {
                if (cb     > R0) s[f][0] = -INFINITY;
                if (cb + 1 > R0) s[f][1] = -INFINITY;
                if (cb     > R1) s[f][2] = -INFINITY;
                if (cb + 1 > R1) s[f][3] = -INFINITY;
            }
            mx0 = fmaxf(mx0, fmaxf(s[f][0], s[f][1]));
            mx1 = fmaxf(mx1, fmaxf(s[f][2], s[f][3]));
        }
        mx0 = fmaxf(mx0, __shfl_xor_sync(0xffffffffu, mx0, 1));
        mx0 = fmaxf(mx0, __shfl_xor_sync(0xffffffffu, mx0, 2));
        mx1 = fmaxf(mx1, __shfl_xor_sync(0xffffffffu, mx1, 1));
        mx1 = fmaxf(mx1, __shfl_xor_sync(0xffffffffu, mx1, 2));
        float mn0 = fmaxf(mr0, mx0), mn1 = fmaxf(mr1, mx1);
        float al0 = __expf(mr0 - mn0), al1 = __expf(mr1 - mn1);
        mr0 = mn0; mr1 = mn1;

        unsigned P[4][4];
        float ps0 = 0.f, ps1 = 0.f;
#pragma unroll
        for (int f = 0; f < 8; f++) {
            float p0 = __expf(s[f][0] - mn0);
            float p1 = __expf(s[f][1] - mn0);
            float p2 = __expf(s[f][2] - mn1);
            float p3 = __expf(s[f][3] - mn1);
            ps0 += p0 + p1; ps1 += p2 + p3;
            __nv_bfloat162 b0 = __floats2bfloat162_rn(p0, p1);
            __nv_bfloat162 b1 = __floats2bfloat162_rn(p2, p3);
            P[f >> 1][(f & 1) * 2]     = *reinterpret_cast<unsigned*>(&b0);
            P[f >> 1][(f & 1) * 2 + 1] = *reinterpret_cast<unsigned*>(&b1);
        }
        ps0 += __shfl_xor_sync(0xffffffffu, ps0, 1);
        ps0 += __shfl_xor_sync(0xffffffffu, ps0, 2);
        ps1 += __shfl_xor_sync(0xffffffffu, ps1, 1);
        ps1 += __shfl_xor_sync(0xffffffffu, ps1, 2);
        l0 = l0 * al0 + ps0;
        l1 = l1 * al1 + ps1;
#pragma unroll
        for (int f = 0; f < 8; f++) {
            o[f][0] *= al0; o[f][1] *= al0;
            o[f][2] *= al1; o[f][3] *= al1;
        }

#pragma unroll
        for (int c = 0; c < 4; c++) {
#pragma unroll
            for (int j = 0; j < 4; j++) {
                unsigned d[4];
                int row = c * 16 + (g & 1) * 8 + li;
                int col = j * 16 + (g >> 1) * 8;
                ldsm4t(d, (unsigned)__cvta_generic_to_shared(&Vs[row * LDH + col]));
                mma16816(o[2 * j],     P[c], d[0], d[1]);
                mma16816(o[2 * j + 1], P[c], d[2], d[3]);
            }
        }
    }

    float i0 = 1.f / l0, i1 = 1.f / l1;
#pragma unroll
    for (int f = 0; f < 8; f++) {
        int col = h * HD + f * 8 + (lane & 3) * 2;
        __nv_bfloat162 v0 = __floats2bfloat162_rn(o[f][0] * i0, o[f][1] * i0);
        __nv_bfloat162 v1 = __floats2bfloat162_rn(o[f][2] * i1, o[f][3] * i1);
        *(unsigned*)&g_attnb[(size_t)R0 * (NH * HD) + col] = *reinterpret_cast<unsigned*>(&v0);
        *(unsigned*)&g_attnb[(size_t)R1 * (NH * HD) + col] = *reinterpret_cast<unsigned*>(&v1);
    }
}

// ---------------------------------------------------------------------------
// Routing
// ---------------------------------------------------------------------------
__global__ void k_zero() {
    int i = threadIdx.x;
    if (i < NE) { g_cnt[i] = 0; g_fill[i] = 0; }
}

__global__ void k_route(const float* __restrict__ H2, const float* __restrict__ Wg) {
    int t = blockIdx.x;
    int e = threadIdx.x;
    __shared__ float sh[HID];
    for (int i = e; i < HID; i += 64) sh[i] = H2[(size_t)t * HID + i];
    __syncthreads();
    float a0 = 0, a1 = 0, a2 = 0, a3 = 0;
    for (int k = 0; k < HID; k += 4) {
        a0 += sh[k]     * Wg[(size_t)k       * NE + e];
        a1 += sh[k + 1] * Wg[(size_t)(k + 1) * NE + e];
        a2 += sh[k + 2] * Wg[(size_t)(k + 2) * NE + e];
        a3 += sh[k + 3] * Wg[(size_t)(k + 3) * NE + e];
    }
    __shared__ float logits[NE];
    logits[e] = (a0 + a1) + (a2 + a3);
    __syncthreads();
    if (e == 0) {
        float sv[NG]; int si[NG];
#pragma unroll
        for (int gg = 0; gg < NG; gg++) {
            float best = logits[gg * 8]; int bi = gg * 8;
#pragma unroll
            for (int j = 1; j < 8; j++) {
                float v = logits[gg * 8 + j];
                if (v > best) { best = v; bi = gg * 8 + j; }
            }
            sv[gg] = best; si[gg] = bi;
        }
        float m = sv[0];
#pragma unroll
        for (int gg = 1; gg < NG; gg++) m = fmaxf(m, sv[gg]);
        float sum = 0.f, p[NG];
#pragma unroll
        for (int gg = 0; gg < NG; gg++) { p[gg] = expf(sv[gg] - m); sum += p[gg]; }
        float is = 1.f / sum;
#pragma unroll
        for (int gg = 0; gg < NG; gg++) {
            g_selid[t * NG + gg] = si[gg];
            g_selw [t * NG + gg] = p[gg] * is;
            atomicAdd(&g_cnt[si[gg]], 1);
        }
    }
}

__global__ void k_scan() {  // pad to 128 (MoE BM)
    int s = 0;
    for (int e = 0; e < NE; e++) { g_off[e] = s; s += (g_cnt[e] + BM - 1) & ~(BM - 1); }
    g_total = s;
}

__global__ void k_scatter() {
    int t = blockIdx.x, gg = threadIdx.x;
    int e = g_selid[t * NG + gg];
    int slot = atomicAdd(&g_fill[e], 1);
    int row = g_off[e] + slot;
    g_tok[row] = t;
    g_w[row]   = g_selw[t * NG + gg];
}

// ---------------------------------------------------------------------------
// MoE GEMM 1: BM=128, BN=128 (64 gate + 64 up cols). A via cp.async,
// B via LDG + in-loop fp32->bf16 convert. Fused silu epilogue.
// ---------------------------------------------------------------------------
#define MOE1_SMEM 67584   // max(pipeline 37888, epilogue 128*132*4)
__global__ void __launch_bounds__(256) k_moe1(const __nv_bfloat16* __restrict__ Ab,
                                              const float* __restrict__ Wgu) {
    extern __shared__ __align__(16) char dyn1[];
    __shared__ int stok[BM];
    __nv_bfloat16* As = (__nv_bfloat16*)dyn1;                    // 2 x BM*LDA_S
    __nv_bfloat16* Bs = (__nv_bfloat16*)(dyn1 + 2 * BM * LDA_S * 2);
    float* Ebuf = (float*)dyn1;                                  // epilogue alias

    int e = blockIdx.z;
    int cnt = g_cnt[e];
    int m0 = blockIdx.y * BM;
    if (m0 >= cnt) return;
    int off = g_off[e];
    int n0 = blockIdx.x * 64;
    const float* B = Wgu + (size_t)e * (HID * 1024);

    int tid = threadIdx.x;
    int warp = tid >> 5;
    int wm = warp & 3, wn = warp >> 2;
    if (tid < BM) stok[tid] = (m0 + tid < cnt) ? g_tok[off + m0 + tid] : -1;
    __syncthreads();

    int a_r = tid >> 2, a_c = (tid & 3) * 8;
    int b_r = tid >> 4, b_c = (tid & 15) * 8;
    int tk0 = stok[a_r], tk1 = stok[a_r + 64];
    const __nv_bfloat16* a0 = Ab + (size_t)((tk0 >= 0) ? tk0 : 0) * HID + a_c;
    const __nv_bfloat16* a1 = Ab + (size_t)((tk1 >= 0) ? tk1 : 0) * HID + a_c;
    int colg = (b_c < 64) ? (n0 + b_c) : (512 + n0 + b_c - 64);
    unsigned dA0 = (unsigned)__cvta_generic_to_shared(&As[a_r * LDA_S + a_c]);
    unsigned dA1 = (unsigned)__cvta_generic_to_shared(&As[(a_r + 64) * LDA_S + a_c]);
    const unsigned szA = BM * LDA_S * 2;

    FragC acc[2][4];
#pragma unroll
    for (int i = 0; i < 2; i++)
#pragma unroll
        for (int j = 0; j < 4; j++) wmma::fill_fragment(acc[i][j], 0.f);

    float4 rb0a, rb0b, rb1a, rb1b;
    auto cpA = [&](int buf, int k0) {
        cp16z(dA0 + buf * szA, a0 + k0, tk0 >= 0);
        cp16z(dA1 + buf * szA, a1 + k0, tk1 >= 0);
        CP_COMMIT();
    };
    auto ldgB = [&](int k0) {
        const float* p0 = &B[(size_t)(k0 + b_r) * 1024 + colg];
        rb0a = *(const float4*)p0; rb0b = *(const float4*)(p0 + 4);
        const float* p1 = &B[(size_t)(k0 + b_r + 16) * 1024 + colg];
        rb1a = *(const float4*)p1; rb1b = *(const float4*)(p1 + 4);
    };
    auto stsB = [&](int buf) {
        *(uint4*)&Bs[buf * BK * LDB_S + b_r * LDB_S + b_c] = f8_to_bf8(rb0a, rb0b);
        *(uint4*)&Bs[buf * BK * LDB_S + (b_r + 16) * LDB_S + b_c] = f8_to_bf8(rb1a, rb1b);
    };

    const int niter = HID / BK;
    cpA(0, 0); ldgB(0); stsB(0);
    cp_wait<0>(); __syncthreads();
    for (int it = 0; it < niter; it++) {
        if (it + 1 < niter) { cpA((it + 1) & 1, (it + 1) * BK); ldgB((it + 1) * BK); }
        mma_tile(As + (it & 1) * BM * LDA_S, Bs + (it & 1) * BK * LDB_S, acc, wm, wn);
        if (it + 1 < niter) { stsB((it + 1) & 1); cp_wait<0>(); __syncthreads(); }
    }

    // ---- fused activation epilogue ----
    __syncthreads();   // all warps done reading pipeline smem before alias reuse
#pragma unroll
    for (int i = 0; i < 2; i++)
#pragma unroll
        for (int j = 0; j < 4; j++)
            wmma::store_matrix_sync(Ebuf + (wm * 32 + i * 16) * 132 + wn * 64 + j * 16,
                                    acc[i][j], 132, wmma::mem_row_major);
    __syncthreads();

    int r  = tid >> 1;
    int c0 = (tid & 1) * 32;
    float wt = (m0 + r < cnt) ? g_w[off + m0 + r] : 0.f;
    unsigned vals[16];
#pragma unroll
    for (int q = 0; q < 16; q++) {
        float g0 = Ebuf[r * 132 + c0 + q * 2];
        float g1 = Ebuf[r * 132 + c0 + q * 2 + 1];
        float u0 = Ebuf[r * 132 + 64 + c0 + q * 2];
        float u1 = Ebuf[r * 132 + 64 + c0 + q * 2 + 1];
        float x0 = g0 / (1.f + __expf(-g0)) * u0 * wt;
        float x1 = g1 / (1.f + __expf(-g1)) * u1 * wt;
        __nv_bfloat162 p = __floats2bfloat162_rn(x0, x1);
        vals[q] = *reinterpret_cast<unsigned*>(&p);
    }
    uint4* dst = (uint4*)&g_actb[(size_t)(off + m0 + r) * INTER + n0 + c0];
#pragma unroll
    for (int q = 0; q < 4; q++)
        dst[q] = make_uint4(vals[q * 4], vals[q * 4 + 1], vals[q * 4 + 2], vals[q * 4 + 3]);
}

// ---------------------------------------------------------------------------
// MoE GEMM 2: BM=128, A via cp.async, staged atomic scatter-add.
// ---------------------------------------------------------------------------
__global__ void __launch_bounds__(256) k_moe2(const float* __restrict__ Wd,
                                              float* __restrict__ out) {
    int e = blockIdx.z;
    int cnt = g_cnt[e];
    int m0 = blockIdx.y * BM;
    if (m0 >= cnt) return;
    int off = g_off[e];
    int n0 = blockIdx.x * BN;
    const float* B = Wd + (size_t)e * (INTER * HID);

    __shared__ __nv_bfloat16 As[2][BM * LDA_S];
    __shared__ __nv_bfloat16 Bs[2][BK * LDB_S];
    __shared__ float stage_s[8 * 272];
    __shared__ int stok[BM];
    int tid = threadIdx.x;
    int lane = tid & 31;
    int warp = tid >> 5;
    int wm = warp & 3, wn = warp >> 2;
    if (tid < BM) stok[tid] = (m0 + tid < cnt) ? g_tok[off + m0 + tid] : -1;
    __syncthreads();

    int a_r = tid >> 2, a_c = (tid & 3) * 8;
    int b_r = tid >> 4, b_c = (tid & 15) * 8;
    const __nv_bfloat16* a0 = g_actb + (size_t)(off + m0 + a_r) * INTER + a_c;
    const __nv_bfloat16* a1 = g_actb + (size_t)(off + m0 + a_r + 64) * INTER + a_c;
    unsigned dA0 = (unsigned)__cvta_generic_to_shared(&As[0][a_r * LDA_S + a_c]);
    unsigned dA1 = (unsigned)__cvta_generic_to_shared(&As[0][(a_r + 64) * LDA_S + a_c]);
    const unsigned szA = BM * LDA_S * 2;

    FragC acc[2][4];
#pragma unroll
    for (int i = 0; i < 2; i++)
#pragma unroll
        for (int j = 0; j < 4; j++) wmma::fill_fragment(acc[i][j], 0.f);

    float4 rb0a, rb0b, rb1a, rb1b;
    auto cpA = [&](int buf, int k0) {
        // padding rows of g_actb hold zeros (moe1 wrote them with wt=0)
        cp16(dA0 + buf * szA, a0 + k0);
        cp16(dA1 + buf * szA, a1 + k0);
        CP_COMMIT();
    };
    auto ldgB = [&](int k0) {
        const float* p0 = &B[(size_t)(k0 + b_r) * HID + n0 + b_c];
        rb0a = *(const float4*)p0; rb0b = *(const float4*)(p0 + 4);
        const float* p1 = &B[(size_t)(k0 + b_r + 16) * HID + n0 + b_c];
        rb1a = *(const float4*)p1; rb1b = *(const float4*)(p1 + 4);
    };
    auto stsB = [&](int buf) {
        *(uint4*)&Bs[buf][b_r * LDB_S + b_c] = f8_to_bf8(rb0a, rb0b);
        *(uint4*)&Bs[buf][(b_r + 16) * LDB_S + b_c] = f8_to_bf8(rb1a, rb1b);
    };

    const int niter = INTER / BK;
    cpA(0, 0); ldgB(0); stsB(0);
    cp_wait<0>(); __syncthreads();
    for (int it = 0; it < niter; it++) {
        if (it + 1 < niter) { cpA((it + 1) & 1, (it + 1) * BK); ldgB((it + 1) * BK); }
        mma_tile(As[it & 1], Bs[it & 1], acc, wm, wn);
        if (it + 1 < niter) { stsB((it + 1) & 1); cp_wait<0>(); __syncthreads(); }
    }

#pragma unroll
    for (int i = 0; i < 2; i++) {
#pragma unroll
        for (int j = 0; j < 4; j++) {
            wmma::store_matrix_sync(&stage_s[warp * 272], acc[i][j], 16, wmma::mem_row_major);
            __syncwarp();
#pragma unroll
            for (int q = 0; q < 8; q++) {
                int el = lane + q * 32;
                int r = el >> 4, c = el & 15;
                int lr = wm * 32 + i * 16 + r;
                if (m0 + lr < cnt) {
                    int tk = stok[lr];
                    atomicAdd(&out[(size_t)tk * HID + n0 + wn * 64 + j * 16 + c],
                              stage_s[warp * 272 + r * 16 + c]);
                }
            }
            __syncwarp();
        }
    }
}

// ---------------------------------------------------------------------------
// Launch
// ---------------------------------------------------------------------------
extern "C" void kernel_launch(void* const* d_in, const int* in_sizes, int n_in,
                              void* d_out, int out_size) {
    const int*   positions = (const int*)  d_in[0];
    const float* hidden    = (const float*)d_in[1];
    const float* Wqkv      = (const float*)d_in[2];
    const float* Wo        = (const float*)d_in[3];
    const float* qnw       = (const float*)d_in[4];
    const float* knw       = (const float*)d_in[5];
    const float* inln      = (const float*)d_in[6];
    const float* postln    = (const float*)d_in[7];
    const float* Wg        = (const float*)d_in[8];
    const float* Wgu       = (const float*)d_in[9];
    const float* Wd        = (const float*)d_in[10];
    float* out = (float*)d_out;

    __nv_bfloat16 *p_hb, *p_attnb, *p_h2b;
    float *p_qkv, *p_h2;
    cudaGetSymbolAddress((void**)&p_hb,    g_hb);
    cudaGetSymbolAddress((void**)&p_qkv,   g_qkv);
    cudaGetSymbolAddress((void**)&p_h2,    g_h2);
    cudaGetSymbolAddress((void**)&p_h2b,   g_h2b);
    cudaGetSymbolAddress((void**)&p_attnb, g_attnb);

    cudaFuncSetAttribute(k_moe1, cudaFuncAttributeMaxDynamicSharedMemorySize, MOE1_SMEM);

    k_rmsnorm<<<T_TOK, 256>>>(hidden, inln, nullptr, p_hb);
    k_gemm_bf16<<<dim3(QKV_N / BN, T_TOK / BM), 256>>>(p_hb, Wqkv, p_qkv, nullptr,
                                                       T_TOK, QKV_N, HID);
    k_qk_prep<<<T_TOK, dim3(32, NH + 2 * NKV)>>>(positions, qnw, knw);
    k_attn_mma<<<dim3(T_TOK / 64, NH), 128>>>();
    k_gemm_bf16<<<dim3(HID / BN, T_TOK / BM), 256>>>(p_attnb, Wo, out, hidden,
                                                     T_TOK, HID, NH * HD);
    k_rmsnorm<<<T_TOK, 256>>>(out, postln, p_h2, p_h2b);
    k_zero<<<1, 64>>>();
    k_route<<<T_TOK, 64>>>(p_h2, Wg);
    k_scan<<<1, 1>>>();
    k_scatter<<<T_TOK, 8>>>();
    // grouped gate_up GEMM (A cp.async) + fused activation
    k_moe1<<<dim3(8, 8, NE), 256, MOE1_SMEM>>>(p_h2b, Wgu);
    // grouped down GEMM (A cp.async), scatter-add into d_out
    k_moe2<<<dim3(HID / BN, 8, NE), 256>>>(Wd, out);
}